// round 12
// baseline (speedup 1.0000x reference)
#include <cuda_runtime.h>

#define Bb 8
#define Ss 384
#define HIDD 512
#define NHh 8
#define HDd 64
#define RR (Bb*Ss)            // 3072 rows
#define ISCALE 0.044194173824159216f       // 1/sqrt(512)
#define ISC2   0.063763263477419631f       // ISCALE * log2(e)

// ---- scratch (device globals; no allocation allowed) ----
static __device__ __align__(16) unsigned g_af[192*64*128];   // enc A-frags [rblk192][kk64][128]
static __device__ __align__(16) unsigned g_wf[4*64*64*64];   // W B-frags  [mat4][nb64][kk64][64]
static __device__ __align__(16) unsigned g_qf[NHh*RR*HDd];   // Q A-frags  [h][rblk192][kk8][128]
static __device__ __align__(16) unsigned g_kf[NHh*RR*HDd];   // K B-frags  [h][kt48][nb8][kk8][64]
static __device__ __align__(16) unsigned g_vf[NHh*RR*HDd];   // V B-frags  [h][kt48][db8][kk8][64]
static __device__ __align__(16) unsigned g_cf[192*64*128];   // ctx A-frags [rblk192][kk64][128]
static __device__ float g_tmp[RR*HIDD];

__device__ __forceinline__ unsigned f2tf32(float x) {
    unsigned u; asm("cvt.rna.tf32.f32 %0, %1;" : "=r"(u) : "f"(x)); return u;
}

__device__ __forceinline__ void mma_tf32(float d[4], uint4 a, uint2 b) {
    asm volatile(
      "mma.sync.aligned.m16n8k8.row.col.f32.tf32.tf32.f32 "
      "{%0,%1,%2,%3}, {%4,%5,%6,%7}, {%8,%9}, {%0,%1,%2,%3};\n"
      : "+f"(d[0]), "+f"(d[1]), "+f"(d[2]), "+f"(d[3])
      : "r"(a.x), "r"(a.y), "r"(a.z), "r"(a.w), "r"(b.x), "r"(b.y));
}

__device__ __forceinline__ void cp16(unsigned dst_smem, const void* src) {
    asm volatile("cp.async.cg.shared.global [%0], [%1], 16;\n"
                 :: "r"(dst_smem), "l"(src));
}
#define CP_COMMIT asm volatile("cp.async.commit_group;\n" ::: "memory")
#define CP_WAIT1  asm volatile("cp.async.wait_group 1;\n" ::: "memory")
#define CP_WAIT0  asm volatile("cp.async.wait_group 0;\n" ::: "memory")

// ============================================================
// Kernel 0: convert enc -> A-frags, Wq/Wk/Wv/Wo -> B-frags (once).
// ============================================================
__global__ __launch_bounds__(256) void prep_kernel(
    const float* __restrict__ enc, const float* __restrict__ Wq,
    const float* __restrict__ Wk,  const float* __restrict__ Wv,
    const float* __restrict__ Wo)
{
    __shared__ float Ts[64][68];
    int tid = threadIdx.x, lane = tid & 31;
    int bid = blockIdx.x;

    if (bid < 384) {
        int m0 = (bid >> 3) * 64, k0 = (bid & 7) * 64;
        int r = tid >> 2;
        #pragma unroll
        for (int i = 0; i < 4; i++) {
            int c = ((tid & 3) + 4*i) * 4;
            *(float4*)&Ts[r][c] = *(const float4*)(enc + (size_t)(m0 + r)*HIDD + k0 + c);
        }
        __syncthreads();
        #pragma unroll
        for (int i = 0; i < 4; i++) {
            int f = (tid >> 5) + 8*i;
            int rblk = f >> 3, kk = f & 7;
            unsigned a[4];
            #pragma unroll
            for (int rg = 0; rg < 4; rg++) {
                int rr = (lane >> 2) + 8*(rg & 1);
                int kb = (lane & 3) + 4*(rg >> 1);
                a[rg] = f2tf32(Ts[rblk*16 + rr][kk*8 + kb]);
            }
            size_t idx = ((size_t)((m0 >> 4) + rblk) * 64 + (k0 >> 3) + kk) * 128 + lane*4;
            *(uint4*)&g_af[idx] = make_uint4(a[0], a[1], a[2], a[3]);
        }
    } else {
        int wb2 = bid - 384;
        int mat = wb2 >> 6, t64 = wb2 & 63;
        int n0 = (t64 >> 3) * 64, k0 = (t64 & 7) * 64;
        const float* W = (mat == 0) ? Wq : (mat == 1) ? Wk : (mat == 2) ? Wv : Wo;
        int r = tid >> 2;
        #pragma unroll
        for (int i = 0; i < 4; i++) {
            int c = ((tid & 3) + 4*i) * 4;
            *(float4*)&Ts[r][c] = *(const float4*)(W + (size_t)(n0 + r)*HIDD + k0 + c);
        }
        __syncthreads();
        #pragma unroll
        for (int i = 0; i < 8; i++) {
            int f = (tid >> 5) + 8*i;
            int nb = f >> 3, kk = f & 7;
            unsigned b[2];
            #pragma unroll
            for (int rg = 0; rg < 2; rg++) {
                int nn = lane >> 2;
                int kb = (lane & 3) + 4*rg;
                b[rg] = f2tf32(Ts[nb*8 + nn][kk*8 + kb]);
            }
            size_t idx = ((size_t)(mat*64 + (n0 >> 3) + nb) * 64 + (k0 >> 3) + kk) * 64 + lane*2;
            *(uint2*)&g_wf[idx] = make_uint2(b[0], b[1]);
        }
    }
}

// ============================================================
// Kernel 1: Q/K/V projections, z-FUSED: one block computes Q,K,V
// for its (head, m-tile); A staged once per chunk.
// grid (8 heads, 48 m-tiles), block 256, dyn smem 64 KB
// ============================================================
__global__ __launch_bounds__(256) void qkv_kernel()
{
    extern __shared__ unsigned dsm[];   // 2 bufs x 8192 words: [A 2048 | W 3x2048]

    int h = blockIdx.x, m0 = blockIdx.y * 64;
    int tid = threadIdx.x, lane = tid & 31, wid = tid >> 5;
    int wr = wid >> 1, wc = wid & 1;

    const unsigned* abase = g_af + (size_t)(m0 >> 4)*64*128;

    auto stage = [&](int c, int buf) {
        unsigned base = buf * 8192;
        #pragma unroll
        for (int s = 0; s < 2; s++) {
            int u = tid + 256*s;                 // uint4 idx 0..511
            int rblk = u >> 7, kk = (u >> 5) & 3, l = u & 31;
            unsigned dst = (unsigned)__cvta_generic_to_shared(dsm + base + u*4);
            cp16(dst, abase + (size_t)(rblk*64 + c*4 + kk)*128 + l*4);
        }
        #pragma unroll
        for (int z = 0; z < 3; z++) {
            #pragma unroll
            for (int s = 0; s < 2; s++) {
                int u = tid + 256*s;             // uint4 idx 0..511
                int nb = u >> 6, kk = (u >> 4) & 3, l = u & 15;
                unsigned dst = (unsigned)__cvta_generic_to_shared(
                    dsm + base + 2048 + z*2048 + u*4);
                cp16(dst, g_wf + ((size_t)(z*64 + h*8 + nb)*64 + c*4 + kk)*64 + l*4);
            }
        }
        CP_COMMIT;
    };

    float facc[3][4][4] = {};

    stage(0, 0);
    for (int c = 0; c < 16; c++) {
        __syncthreads();
        if (c + 1 < 16) { stage(c + 1, (c + 1) & 1); CP_WAIT1; }
        else            { CP_WAIT0; }
        __syncthreads();
        unsigned base = (c & 1) * 8192;
        const unsigned* A = dsm + base;
        const unsigned* W = dsm + base + 2048;
        #pragma unroll
        for (int kk = 0; kk < 4; kk++) {
            uint4 aa = *(const uint4*)(A + wr*512 + kk*128 + lane*4);
            #pragma unroll
            for (int z = 0; z < 3; z++) {
                #pragma unroll
                for (int nt = 0; nt < 4; nt++) {
                    uint2 bb = *(const uint2*)(W + z*2048
                                + ((wc*4 + nt)*4 + kk)*64 + lane*2);
                    mma_tf32(facc[z][nt], aa, bb);
                }
            }
        }
    }

    int q2 = lane & 3, r4 = lane >> 2;
    #pragma unroll
    for (int z = 0; z < 3; z++) {
        unsigned* outp = (z == 0) ? g_qf : ((z == 1) ? g_kf : g_vf);
        #pragma unroll
        for (int nt = 0; nt < 4; nt++) {
            #pragma unroll
            for (int hi = 0; hi < 2; hi++) {
                #pragma unroll
                for (int j = 0; j < 2; j++) {
                    unsigned tv = f2tf32(facc[z][nt][2*hi + j]);
                    int d = wc*32 + nt*8 + 2*q2 + j;
                    int rtile = 16*wr + r4 + 8*hi;
                    size_t idx;
                    if (z == 0) {                   // Q: A-frag
                        int rr = rtile & 15;
                        idx = ((size_t)(h*192 + (m0 >> 4) + wr)*8 + (d >> 3))*128
                            + (size_t)(4*(rr & 7) + (d & 3))*4 + (rr >> 3) + 2*((d >> 2) & 1);
                    } else if (z == 1) {            // K: B-frag (n=key, k=d)
                        int nb = rtile >> 3;
                        idx = (size_t)(h*48 + (m0 >> 6))*4096
                            + ((size_t)(nb*8 + (d >> 3))*32 + 4*(rtile & 7) + (d & 3))*2
                            + ((d >> 2) & 1);
                    } else {                        // V: B-frag (n=d, k=key)
                        int db = d >> 3, kkv = rtile >> 3;
                        idx = (size_t)(h*48 + (m0 >> 6))*4096
                            + ((size_t)(db*8 + kkv)*32 + 4*(d & 7) + (rtile & 3))*2
                            + ((rtile >> 2) & 1);
                    }
                    outp[idx] = tv;
                }
            }
        }
    }
}

// ============================================================
// Kernel 2: attention, fused A+B, heavy-first order.
// Phase A: register row-sum accumulation (one reduce at end).
// Phase B: direct w-write from accumulators (stcs), Ps only for PV.
// grid 384: class c = bid/64 (nj = 6-c), h = bid%8, bq = (bid%64)/8
// ============================================================
__global__ __launch_bounds__(256) void attn_kernel(float* __restrict__ w_out)
{
    extern __shared__ unsigned dsm[];
    unsigned* KV = dsm;                               // 2 bufs x 8192 (K | V)
    float (*Ps)[68] = (float(*)[68])(dsm + 16384);
    float* ls  = (float*)(dsm + 16384) + 64*68;
    float* lrl = ls + 64;

    int tid = threadIdx.x, lane = tid & 31, wid = tid >> 5;
    int wr = wid >> 1, wc = wid & 1;

    // heavy-first mapping
    int bid = blockIdx.x;
    int c   = bid >> 6;            // 0..5
    int nj  = 6 - c;               // heaviest first
    int e   = bid & 63;
    int h   = e & 7, bq = e >> 3;
    int s0  = (nj - 1) * 64;
    int r0  = bq * Ss + s0;
    int nv  = 8 * nj;

    int q2 = lane & 3, r4 = lane >> 2;
    int rlo = 16*wr + r4;
    int lrr = tid >> 4, lcc = (tid & 15) * 4;

    if (tid < 64) ls[tid] = 0.f;

    // Q fragments resident in registers
    uint4 qa[8];
    const unsigned* qb = g_qf + (size_t)((h*192 + (r0 >> 4) + wr)*8)*128;
    #pragma unroll
    for (int kk = 0; kk < 8; kk++) qa[kk] = *(const uint4*)(qb + kk*128 + lane*4);

    // masked tiles: zero w-writes up front (streaming)
    for (int kb = 0; kb < 8; kb++)
        for (int j = nj; j < 6; j++) {
            size_t wrow = ((size_t)((bq*NHh + h)*Bb + kb)) * Ss;
            float4 z = make_float4(0.f, 0.f, 0.f, 0.f);
            #pragma unroll
            for (int i = 0; i < 4; i++)
                __stcs((float4*)(w_out + (wrow + s0 + lrr + 16*i) * Ss + j*64 + lcc), z);
        }

    auto stageK = [&](int v, int buf) {
        int kt = (v/nj)*6 + (v % nj);
        const unsigned* src = g_kf + (size_t)(h*48 + kt)*4096;
        #pragma unroll
        for (int s = 0; s < 4; s++) {
            unsigned dst = (unsigned)__cvta_generic_to_shared(KV + buf*8192 + s*1024 + tid*4);
            cp16(dst, src + s*1024 + tid*4);
        }
        CP_COMMIT;
    };
    auto stageKV = [&](int v, int buf) {
        int kt = (v/nj)*6 + (v % nj);
        const unsigned* ks = g_kf + (size_t)(h*48 + kt)*4096;
        const unsigned* vs = g_vf + (size_t)(h*48 + kt)*4096;
        #pragma unroll
        for (int s = 0; s < 4; s++) {
            unsigned dk = (unsigned)__cvta_generic_to_shared(KV + buf*8192 + s*1024 + tid*4);
            unsigned dv = (unsigned)__cvta_generic_to_shared(KV + buf*8192 + 4096 + s*1024 + tid*4);
            cp16(dk, ks + s*1024 + tid*4);
            cp16(dv, vs + s*1024 + tid*4);
        }
        CP_COMMIT;
    };

    // -------- phase A: row sums accumulated in REGISTERS --------
    float l_lo = 0.f, l_hi = 0.f;
    stageK(0, 0);
    for (int v = 0; v < nv; v++) {
        __syncthreads();
        if (v + 1 < nv) { stageK(v + 1, (v + 1) & 1); CP_WAIT1; }
        else            { CP_WAIT0; }
        __syncthreads();
        const unsigned* Kf = KV + (v & 1)*8192;
        int kp0 = (v % nj) * 64;

        float sacc[4][4] = {};
        #pragma unroll
        for (int nt = 0; nt < 4; nt++) {
            int nb = wc*4 + nt;
            #pragma unroll
            for (int kk = 0; kk < 8; kk++) {
                uint2 bb = *(const uint2*)(Kf + (nb*8 + kk)*64 + lane*2);
                mma_tf32(sacc[nt], qa[kk], bb);
            }
        }

        bool diag = (kp0 == s0);
        #pragma unroll
        for (int nt = 0; nt < 4; nt++) {
            int cb = wc*32 + nt*8 + 2*q2;
            float p0 = exp2f(sacc[nt][0] * ISC2);
            float p1 = exp2f(sacc[nt][1] * ISC2);
            float p2 = exp2f(sacc[nt][2] * ISC2);
            float p3 = exp2f(sacc[nt][3] * ISC2);
            if (diag) {
                if (cb     > rlo)     p0 = 0.f;
                if (cb + 1 > rlo)     p1 = 0.f;
                if (cb     > rlo + 8) p2 = 0.f;
                if (cb + 1 > rlo + 8) p3 = 0.f;
            }
            l_lo += p0 + p1; l_hi += p2 + p3;
        }
    }
    // one reduce + one atomic per row at the very end
    l_lo += __shfl_xor_sync(0xffffffffu, l_lo, 1);
    l_lo += __shfl_xor_sync(0xffffffffu, l_lo, 2);
    l_hi += __shfl_xor_sync(0xffffffffu, l_hi, 1);
    l_hi += __shfl_xor_sync(0xffffffffu, l_hi, 2);
    if (q2 == 0) { atomicAdd(&ls[rlo], l_lo); atomicAdd(&ls[rlo + 8], l_hi); }

    __syncthreads();
    if (tid < 64) lrl[tid] = -__log2f(ls[tid]);   // log2 domain
    __syncthreads();
    float la = lrl[rlo], lb = lrl[rlo + 8];

    float cacc[4][4] = {};

    // -------- phase B: normalized w (direct stcs) + PV --------
    stageKV(0, 0);
    for (int v = 0; v < nv; v++) {
        __syncthreads();
        if (v + 1 < nv) { stageKV(v + 1, (v + 1) & 1); CP_WAIT1; }
        else            { CP_WAIT0; }
        __syncthreads();
        const unsigned* Kf = KV + (v & 1)*8192;
        const unsigned* Vf = Kf + 4096;
        int kp0 = (v % nj) * 64, kb2 = v / nj;
        size_t wrow = ((size_t)((bq*NHh + h)*Bb + kb2)) * Ss + s0;

        float sacc[4][4] = {};
        #pragma unroll
        for (int nt = 0; nt < 4; nt++) {
            int nb = wc*4 + nt;
            #pragma unroll
            for (int kk = 0; kk < 8; kk++) {
                uint2 bb = *(const uint2*)(Kf + (nb*8 + kk)*64 + lane*2);
                mma_tf32(sacc[nt], qa[kk], bb);
            }
        }

        bool diag = (kp0 == s0);
        #pragma unroll
        for (int nt = 0; nt < 4; nt++) {
            int cb = wc*32 + nt*8 + 2*q2;
            float p0 = exp2f(fmaf(sacc[nt][0], ISC2, la));
            float p1 = exp2f(fmaf(sacc[nt][1], ISC2, la));
            float p2 = exp2f(fmaf(sacc[nt][2], ISC2, lb));
            float p3 = exp2f(fmaf(sacc[nt][3], ISC2, lb));
            if (diag) {
                if (cb     > rlo)     p0 = 0.f;
                if (cb + 1 > rlo)     p1 = 0.f;
                if (cb     > rlo + 8) p2 = 0.f;
                if (cb + 1 > rlo + 8) p3 = 0.f;
            }
            // direct streaming w write from registers (full 32B sectors)
            __stcs((float2*)(w_out + (wrow + rlo)     * Ss + kp0 + cb), make_float2(p0, p1));
            __stcs((float2*)(w_out + (wrow + rlo + 8) * Ss + kp0 + cb), make_float2(p2, p3));
            // Ps only feeds PV now
            *(float2*)&Ps[rlo][cb]     = make_float2(p0, p1);
            *(float2*)&Ps[rlo + 8][cb] = make_float2(p2, p3);
        }
        __syncthreads();

        // ctx += P V  (P as raw fp32 bits -> tf32 truncation)
        #pragma unroll
        for (int kk = 0; kk < 8; kk++) {
            int k0 = kk * 8;
            uint4 pa;
            pa.x = __float_as_uint(Ps[rlo    ][k0 + q2]);
            pa.y = __float_as_uint(Ps[rlo + 8][k0 + q2]);
            pa.z = __float_as_uint(Ps[rlo    ][k0 + 4 + q2]);
            pa.w = __float_as_uint(Ps[rlo + 8][k0 + 4 + q2]);
            #pragma unroll
            for (int nt = 0; nt < 4; nt++) {
                uint2 bb = *(const uint2*)(Vf + ((wc*4 + nt)*8 + kk)*64 + lane*2);
                mma_tf32(cacc[nt], pa, bb);
            }
        }
    }

    // ctx epilogue -> A-frag layout (already normalized)
    int rblkg = (r0 >> 4) + wr;
    #pragma unroll
    for (int nt = 0; nt < 4; nt++) {
        size_t kkg = (size_t)(h*8 + wc*4 + nt);
        #pragma unroll
        for (int hi = 0; hi < 2; hi++) {
            #pragma unroll
            for (int j = 0; j < 2; j++) {
                int kbit = 2*q2 + j;
                int word = (4*r4 + (kbit & 3))*4 + hi + 2*((kbit >> 2) & 1);
                g_cf[((size_t)rblkg*64 + kkg)*128 + word] = f2tf32(cacc[nt][2*hi + j]);
            }
        }
    }
}

// ============================================================
// Pipelined 64x64x512 GEMM core (R7-proven, for out_kernel)
// ============================================================
__device__ __forceinline__ void gemm_pipe(
    const unsigned* __restrict__ abase, const unsigned* __restrict__ wbase,
    unsigned* sA, unsigned* sW, float facc[4][4],
    int tid, int lane, int wr, int wc)
{
    auto stage = [&](int c, int buf) {
        #pragma unroll
        for (int rblk = 0; rblk < 4; rblk++) {
            unsigned dst = (unsigned)__cvta_generic_to_shared(sA + buf*4096 + rblk*1024 + tid*4);
            cp16(dst, abase + (size_t)(rblk*64 + c*8)*128 + tid*4);
        }
        #pragma unroll
        for (int s = 0; s < 4; s++) {
            int idx = tid + 256*s;
            int nb = idx >> 7, rem = idx & 127;
            unsigned dst = (unsigned)__cvta_generic_to_shared(sW + buf*4096 + nb*512 + rem*4);
            cp16(dst, wbase + (size_t)(nb*64 + c*8)*64 + rem*4);
        }
        CP_COMMIT;
    };

    stage(0, 0);
    for (int c = 0; c < 8; c++) {
        __syncthreads();
        if (c + 1 < 8) { stage(c + 1, (c + 1) & 1); CP_WAIT1; }
        else           { CP_WAIT0; }
        __syncthreads();
        const unsigned* A = sA + (c & 1) * 4096;
        const unsigned* W = sW + (c & 1) * 4096;
        #pragma unroll
        for (int kk = 0; kk < 8; kk++) {
            uint4 aa = *(const uint4*)(A + wr*1024 + kk*128 + lane*4);
            #pragma unroll
            for (int nt = 0; nt < 4; nt++) {
                uint2 bb = *(const uint2*)(W + (wc*4 + nt)*512 + kk*64 + lane*2);
                mma_tf32(facc[nt], aa, bb);
            }
        }
    }
}

// ============================================================
// Kernel 3: out_pre = ctx @ Wo^T + enc -> g_tmp (pipelined GEMM)
// grid (8 n-tiles, 48 m-tiles), block 256
// ============================================================
__global__ __launch_bounds__(256) void out_kernel(const float* __restrict__ enc)
{
    extern __shared__ unsigned dsm[];
    unsigned* sA = dsm;
    unsigned* sW = dsm + 8192;

    int n0 = blockIdx.x * 64, m0 = blockIdx.y * 64;
    int tid = threadIdx.x, lane = tid & 31, wid = tid >> 5;
    int wr = wid >> 1, wc = wid & 1;

    float facc[4][4] = {};
    gemm_pipe(g_cf + (size_t)(m0 >> 4)*64*128,
              g_wf + (size_t)(3*64 + (n0 >> 3))*64*64,
              sA, sW, facc, tid, lane, wr, wc);

    int q2 = lane & 3, r4 = lane >> 2;
    #pragma unroll
    for (int nt = 0; nt < 4; nt++) {
        #pragma unroll
        for (int hi = 0; hi < 2; hi++) {
            int row = m0 + 16*wr + r4 + 8*hi;
            int col = n0 + wc*32 + nt*8 + 2*q2;
            float2 e2 = *(const float2*)(enc + (size_t)row * HIDD + col);
            float2 o = make_float2(facc[nt][2*hi] + e2.x, facc[nt][2*hi + 1] + e2.y);
            *(float2*)(g_tmp + (size_t)row * HIDD + col) = o;
        }
    }
}

// ============================================================
// Kernel 4: per-row LayerNorm -> d_out[0 : R*HID]
// ============================================================
__global__ __launch_bounds__(256) void ln_kernel(
    const float* __restrict__ gamma,
    const float* __restrict__ beta,
    float* __restrict__ out)
{
    int r = blockIdx.x;
    int t = threadIdx.x;
    const float* x = g_tmp + (size_t)r * HIDD;
    float v0 = x[t], v1 = x[t + 256];

    __shared__ float red[256];
    red[t] = v0 + v1;
    __syncthreads();
    #pragma unroll
    for (int o = 128; o > 0; o >>= 1) {
        if (t < o) red[t] += red[t + o];
        __syncthreads();
    }
    float mu = red[0] * (1.0f / HIDD);
    __syncthreads();

    float d0 = v0 - mu, d1 = v1 - mu;
    red[t] = d0*d0 + d1*d1;
    __syncthreads();
    #pragma unroll
    for (int o = 128; o > 0; o >>= 1) {
        if (t < o) red[t] += red[t + o];
        __syncthreads();
    }
    float var = red[0] * (1.0f / HIDD);
    float rs = rsqrtf(var + 1e-6f);

    out[(size_t)r * HIDD + t]       = d0 * rs * gamma[t]       + beta[t];
    out[(size_t)r * HIDD + t + 256] = d1 * rs * gamma[t + 256] + beta[t + 256];
}

// ============================================================
// launch
// ============================================================
extern "C" void kernel_launch(void* const* d_in, const int* in_sizes, int n_in,
                              void* d_out, int out_size)
{
    const float* enc   = (const float*)d_in[0];
    // d_in[1] = mask (int32 tril) — reproduced analytically
    const float* Wq    = (const float*)d_in[2];
    const float* Wk    = (const float*)d_in[3];
    const float* Wv    = (const float*)d_in[4];
    const float* Wo    = (const float*)d_in[5];
    const float* gamma = (const float*)d_in[6];
    const float* beta  = (const float*)d_in[7];

    float* out = (float*)d_out;                  // (B,S,HID)
    float* w   = out + (size_t)RR * HIDD;        // (B,NH,B,S,S)

    const int qkv_smem  = 16384 * 4;                         // 64 KB
    const int gemm_smem = 16384 * 4;                         // 64 KB
    const int attn_smem = 16384 * 4 + (64*68 + 128) * 4;     // 83456 B
    cudaFuncSetAttribute(qkv_kernel,  cudaFuncAttributeMaxDynamicSharedMemorySize, qkv_smem);
    cudaFuncSetAttribute(out_kernel,  cudaFuncAttributeMaxDynamicSharedMemorySize, gemm_smem);
    cudaFuncSetAttribute(attn_kernel, cudaFuncAttributeMaxDynamicSharedMemorySize, attn_smem);

    prep_kernel<<<640, 256>>>(enc, Wq, Wk, Wv, Wo);
    qkv_kernel<<<dim3(8, 48), 256, qkv_smem>>>();
    attn_kernel<<<384, 256, attn_smem>>>(w);
    out_kernel<<<dim3(8, 48), 256, gemm_smem>>>(enc);
    ln_kernel<<<RR, 256>>>(gamma, beta, out);
}

// round 13
// speedup vs baseline: 1.2317x; 1.2317x over previous
#include <cuda_runtime.h>
#include <cuda_fp16.h>

#define Bb 8
#define Ss 384
#define HIDD 512
#define NHh 8
#define HDd 64
#define RR (Bb*Ss)            // 3072 rows
#define ISCALE 0.044194173824159216f       // 1/sqrt(512)
#define ISC2   0.063763263477419631f       // ISCALE * log2(e)

// ---- scratch (device globals; no allocation allowed) ----
static __device__ __align__(16) unsigned g_af[192*64*128];     // enc A-frags (tf32)
static __device__ __align__(16) unsigned g_wf[4*64*64*64];     // W B-frags (tf32)
static __device__ __align__(16) unsigned short g_qh[NHh*RR*HDd];  // Q fp16 [h][row][d]
static __device__ __align__(16) unsigned short g_kh[NHh*RR*HDd];  // K fp16 [h][key][d]
static __device__ __align__(16) unsigned short g_vh[NHh*RR*HDd];  // V fp16 [h][key][d]
static __device__ __align__(16) unsigned g_cf[192*64*128];     // ctx A-frags (tf32)
static __device__ float g_tmp[RR*HIDD];

__device__ __forceinline__ unsigned f2tf32(float x) {
    unsigned u; asm("cvt.rna.tf32.f32 %0, %1;" : "=r"(u) : "f"(x)); return u;
}
__device__ __forceinline__ unsigned packh2(float lo, float hi) {
    unsigned u; asm("cvt.rn.f16x2.f32 %0, %1, %2;" : "=r"(u) : "f"(hi), "f"(lo)); return u;
}
__device__ __forceinline__ void mma_tf32(float d[4], uint4 a, uint2 b) {
    asm volatile(
      "mma.sync.aligned.m16n8k8.row.col.f32.tf32.tf32.f32 "
      "{%0,%1,%2,%3}, {%4,%5,%6,%7}, {%8,%9}, {%0,%1,%2,%3};\n"
      : "+f"(d[0]), "+f"(d[1]), "+f"(d[2]), "+f"(d[3])
      : "r"(a.x), "r"(a.y), "r"(a.z), "r"(a.w), "r"(b.x), "r"(b.y));
}
__device__ __forceinline__ void mma_f16(float d[4], const unsigned a[4],
                                        unsigned b0, unsigned b1) {
    asm volatile(
      "mma.sync.aligned.m16n8k16.row.col.f32.f16.f16.f32 "
      "{%0,%1,%2,%3}, {%4,%5,%6,%7}, {%8,%9}, {%0,%1,%2,%3};\n"
      : "+f"(d[0]), "+f"(d[1]), "+f"(d[2]), "+f"(d[3])
      : "r"(a[0]), "r"(a[1]), "r"(a[2]), "r"(a[3]), "r"(b0), "r"(b1));
}
__device__ __forceinline__ void ldsm4(unsigned& r0, unsigned& r1, unsigned& r2,
                                      unsigned& r3, unsigned addr) {
    asm volatile("ldmatrix.sync.aligned.m8n8.x4.shared.b16 {%0,%1,%2,%3}, [%4];"
                 : "=r"(r0), "=r"(r1), "=r"(r2), "=r"(r3) : "r"(addr));
}
__device__ __forceinline__ void ldsm4t(unsigned& r0, unsigned& r1, unsigned& r2,
                                       unsigned& r3, unsigned addr) {
    asm volatile("ldmatrix.sync.aligned.m8n8.x4.trans.shared.b16 {%0,%1,%2,%3}, [%4];"
                 : "=r"(r0), "=r"(r1), "=r"(r2), "=r"(r3) : "r"(addr));
}
__device__ __forceinline__ unsigned swz(unsigned o) { return o ^ ((o >> 3) & 0x70u); }

__device__ __forceinline__ void cp16(unsigned dst_smem, const void* src) {
    asm volatile("cp.async.cg.shared.global [%0], [%1], 16;\n"
                 :: "r"(dst_smem), "l"(src));
}
#define CP_COMMIT asm volatile("cp.async.commit_group;\n" ::: "memory")
#define CP_WAIT1  asm volatile("cp.async.wait_group 1;\n" ::: "memory")
#define CP_WAIT0  asm volatile("cp.async.wait_group 0;\n" ::: "memory")

// ============================================================
// Kernel 0: enc -> A-frags, W -> B-frags (tf32, unchanged)
// ============================================================
__global__ __launch_bounds__(256) void prep_kernel(
    const float* __restrict__ enc, const float* __restrict__ Wq,
    const float* __restrict__ Wk,  const float* __restrict__ Wv,
    const float* __restrict__ Wo)
{
    __shared__ float Ts[64][68];
    int tid = threadIdx.x, lane = tid & 31;
    int bid = blockIdx.x;

    if (bid < 384) {
        int m0 = (bid >> 3) * 64, k0 = (bid & 7) * 64;
        int r = tid >> 2;
        #pragma unroll
        for (int i = 0; i < 4; i++) {
            int c = ((tid & 3) + 4*i) * 4;
            *(float4*)&Ts[r][c] = *(const float4*)(enc + (size_t)(m0 + r)*HIDD + k0 + c);
        }
        __syncthreads();
        #pragma unroll
        for (int i = 0; i < 4; i++) {
            int f = (tid >> 5) + 8*i;
            int rblk = f >> 3, kk = f & 7;
            unsigned a[4];
            #pragma unroll
            for (int rg = 0; rg < 4; rg++) {
                int rr = (lane >> 2) + 8*(rg & 1);
                int kb = (lane & 3) + 4*(rg >> 1);
                a[rg] = f2tf32(Ts[rblk*16 + rr][kk*8 + kb]);
            }
            size_t idx = ((size_t)((m0 >> 4) + rblk) * 64 + (k0 >> 3) + kk) * 128 + lane*4;
            *(uint4*)&g_af[idx] = make_uint4(a[0], a[1], a[2], a[3]);
        }
    } else {
        int wb2 = bid - 384;
        int mat = wb2 >> 6, t64 = wb2 & 63;
        int n0 = (t64 >> 3) * 64, k0 = (t64 & 7) * 64;
        const float* W = (mat == 0) ? Wq : (mat == 1) ? Wk : (mat == 2) ? Wv : Wo;
        int r = tid >> 2;
        #pragma unroll
        for (int i = 0; i < 4; i++) {
            int c = ((tid & 3) + 4*i) * 4;
            *(float4*)&Ts[r][c] = *(const float4*)(W + (size_t)(n0 + r)*HIDD + k0 + c);
        }
        __syncthreads();
        #pragma unroll
        for (int i = 0; i < 8; i++) {
            int f = (tid >> 5) + 8*i;
            int nb = f >> 3, kk = f & 7;
            unsigned b[2];
            #pragma unroll
            for (int rg = 0; rg < 2; rg++) {
                int nn = lane >> 2;
                int kb = (lane & 3) + 4*rg;
                b[rg] = f2tf32(Ts[nb*8 + nn][kk*8 + kb]);
            }
            size_t idx = ((size_t)(mat*64 + (n0 >> 3) + nb) * 64 + (k0 >> 3) + kk) * 64 + lane*2;
            *(uint2*)&g_wf[idx] = make_uint2(b[0], b[1]);
        }
    }
}

// ============================================================
// Kernel 1: Q/K/V projections, z-fused tf32 mainloop; epilogue
// now writes PLAIN fp16 [h][row][d] (half2 per pair).
// grid (8 heads, 48 m-tiles), block 256, dyn smem 64 KB
// ============================================================
__global__ __launch_bounds__(256) void qkv_kernel()
{
    extern __shared__ unsigned dsm[];   // 2 bufs x 8192 words: [A 2048 | W 3x2048]

    int h = blockIdx.x, m0 = blockIdx.y * 64;
    int tid = threadIdx.x, lane = tid & 31, wid = tid >> 5;
    int wr = wid >> 1, wc = wid & 1;

    const unsigned* abase = g_af + (size_t)(m0 >> 4)*64*128;

    auto stage = [&](int c, int buf) {
        unsigned base = buf * 8192;
        #pragma unroll
        for (int s = 0; s < 2; s++) {
            int u = tid + 256*s;
            int rblk = u >> 7, kk = (u >> 5) & 3, l = u & 31;
            unsigned dst = (unsigned)__cvta_generic_to_shared(dsm + base + u*4);
            cp16(dst, abase + (size_t)(rblk*64 + c*4 + kk)*128 + l*4);
        }
        #pragma unroll
        for (int z = 0; z < 3; z++) {
            #pragma unroll
            for (int s = 0; s < 2; s++) {
                int u = tid + 256*s;
                int nb = u >> 6, kk = (u >> 4) & 3, l = u & 15;
                unsigned dst = (unsigned)__cvta_generic_to_shared(
                    dsm + base + 2048 + z*2048 + u*4);
                cp16(dst, g_wf + ((size_t)(z*64 + h*8 + nb)*64 + c*4 + kk)*64 + l*4);
            }
        }
        CP_COMMIT;
    };

    float facc[3][4][4] = {};

    stage(0, 0);
    for (int c = 0; c < 16; c++) {
        __syncthreads();
        if (c + 1 < 16) { stage(c + 1, (c + 1) & 1); CP_WAIT1; }
        else            { CP_WAIT0; }
        __syncthreads();
        unsigned base = (c & 1) * 8192;
        const unsigned* A = dsm + base;
        const unsigned* W = dsm + base + 2048;
        #pragma unroll
        for (int kk = 0; kk < 4; kk++) {
            uint4 aa = *(const uint4*)(A + wr*512 + kk*128 + lane*4);
            #pragma unroll
            for (int z = 0; z < 3; z++) {
                #pragma unroll
                for (int nt = 0; nt < 4; nt++) {
                    uint2 bb = *(const uint2*)(W + z*2048
                                + ((wc*4 + nt)*4 + kk)*64 + lane*2);
                    mma_tf32(facc[z][nt], aa, bb);
                }
            }
        }
    }

    // epilogue: plain fp16 [h][row][d] stores (uniform for Q/K/V)
    int q2 = lane & 3, r4 = lane >> 2;
    #pragma unroll
    for (int z = 0; z < 3; z++) {
        unsigned short* outp = (z == 0) ? g_qh : ((z == 1) ? g_kh : g_vh);
        #pragma unroll
        for (int nt = 0; nt < 4; nt++) {
            int cb = wc*32 + nt*8 + 2*q2;
            #pragma unroll
            for (int hi = 0; hi < 2; hi++) {
                int gr = m0 + 16*wr + r4 + 8*hi;
                unsigned u = packh2(facc[z][nt][2*hi], facc[z][nt][2*hi + 1]);
                *(unsigned*)&outp[((size_t)h*RR + gr)*HDd + cb] = u;
            }
        }
    }
}

// ============================================================
// Kernel 2: attention fp16 (m16n8k16 + ldmatrix), fused A+B,
// heavy-first order, stcs w writes.
// smem words: Qs[0,2048) | buf0 K[2048,4096) V[4096,6144)
//             buf1 K[6144,8192) V[8192,10240) | Ps[10240,12288)
//             ls[12288..] lrl[12352..]   total 12416 w = 49664 B
// ============================================================
__global__ __launch_bounds__(256, 3) void attn_kernel(float* __restrict__ w_out)
{
    extern __shared__ unsigned dsm[];
    unsigned sbase = (unsigned)__cvta_generic_to_shared(dsm);
    float* ls  = (float*)(dsm + 12288);
    float* lrl = (float*)(dsm + 12352);

    int tid = threadIdx.x, lane = tid & 31, wid = tid >> 5;
    int wr = wid >> 1, wc = wid & 1;

    // heavy-first mapping
    int bid = blockIdx.x;
    int c   = bid >> 6;
    int nj  = 6 - c;
    int e   = bid & 63;
    int h   = e & 7, bq = e >> 3;
    int s0  = (nj - 1) * 64;
    int r0  = bq * Ss + s0;
    int nv  = 8 * nj;

    int q2 = lane & 3, r4 = lane >> 2;
    int rlo = 16*wr + r4;
    int lrr = tid >> 4, lcc = (tid & 15) * 4;

    if (tid < 64) ls[tid] = 0.f;

    // stage Q tile (8KB) -> Qs
    {
        const unsigned short* src = g_qh + ((size_t)h*RR + r0)*HDd;
        #pragma unroll
        for (int s = 0; s < 2; s++) {
            int ch = tid + 256*s;             // 0..511 chunks of 16B
            cp16(sbase + swz(ch*16), src + (ch >> 3)*64 + (ch & 7)*8);
        }
        CP_COMMIT;
    }

    // masked tiles: zero w-writes while Q stages
    for (int kb = 0; kb < 8; kb++)
        for (int j = nj; j < 6; j++) {
            size_t wrow = ((size_t)((bq*NHh + h)*Bb + kb)) * Ss;
            float4 z4 = make_float4(0.f, 0.f, 0.f, 0.f);
            #pragma unroll
            for (int i = 0; i < 4; i++)
                __stcs((float4*)(w_out + (wrow + s0 + lrr + 16*i) * Ss + j*64 + lcc), z4);
        }

    CP_WAIT0;
    __syncthreads();

    // Q A-frags resident in registers (4 ks x 4 regs)
    unsigned qa[4][4];
    #pragma unroll
    for (int ks = 0; ks < 4; ks++) {
        unsigned addr = sbase + swz((16*wr + (lane & 15))*128u
                                    + (ks*16 + (lane >> 4)*8)*2u);
        ldsm4(qa[ks][0], qa[ks][1], qa[ks][2], qa[ks][3], addr);
    }

    auto stageK = [&](int v, int buf) {
        int kt = (v/nj)*6 + (v % nj);
        const unsigned short* src = g_kh + ((size_t)h*RR + kt*64)*HDd;
        unsigned kb = sbase + (2048u + buf*4096u)*4u;
        #pragma unroll
        for (int s = 0; s < 2; s++) {
            int ch = tid + 256*s;
            cp16(kb + swz(ch*16), src + (ch >> 3)*64 + (ch & 7)*8);
        }
        CP_COMMIT;
    };
    auto stageKV = [&](int v, int buf) {
        int kt = (v/nj)*6 + (v % nj);
        const unsigned short* ks = g_kh + ((size_t)h*RR + kt*64)*HDd;
        const unsigned short* vs = g_vh + ((size_t)h*RR + kt*64)*HDd;
        unsigned kb = sbase + (2048u + buf*4096u)*4u;
        unsigned vb = kb + 8192u;
        #pragma unroll
        for (int s = 0; s < 2; s++) {
            int ch = tid + 256*s;
            cp16(kb + swz(ch*16), ks + (ch >> 3)*64 + (ch & 7)*8);
            cp16(vb + swz(ch*16), vs + (ch >> 3)*64 + (ch & 7)*8);
        }
        CP_COMMIT;
    };

    // K B-frag address pieces (no-trans: K is [key][d] = col-major B)
    unsigned k_row = (lane & 7);                // within nb block
    unsigned k_cg  = ((lane >> 3) & 3);         // k col-group 0..3

    // -------- phase A: row sums in registers --------
    float l_lo = 0.f, l_hi = 0.f;
    stageK(0, 0);
    for (int v = 0; v < nv; v++) {
        __syncthreads();
        if (v + 1 < nv) { stageK(v + 1, (v + 1) & 1); CP_WAIT1; }
        else            { CP_WAIT0; }
        __syncthreads();
        unsigned kbase = sbase + (2048u + (v & 1)*4096u)*4u;
        int kp0 = (v % nj) * 64;

        float sacc[4][4] = {};
        #pragma unroll
        for (int nt = 0; nt < 4; nt++) {
            unsigned nrow = (wc*4 + nt)*8 + k_row;
            #pragma unroll
            for (int kp = 0; kp < 2; kp++) {
                unsigned b0, b1, b2, b3;
                ldsm4(b0, b1, b2, b3,
                      kbase + swz(nrow*128u + (kp*32 + k_cg*8)*2u));
                mma_f16(sacc[nt], qa[2*kp],     b0, b1);
                mma_f16(sacc[nt], qa[2*kp + 1], b2, b3);
            }
        }

        bool diag = (kp0 == s0);
        #pragma unroll
        for (int nt = 0; nt < 4; nt++) {
            int cb = wc*32 + nt*8 + 2*q2;
            float p0 = exp2f(sacc[nt][0] * ISC2);
            float p1 = exp2f(sacc[nt][1] * ISC2);
            float p2 = exp2f(sacc[nt][2] * ISC2);
            float p3 = exp2f(sacc[nt][3] * ISC2);
            if (diag) {
                if (cb     > rlo)     p0 = 0.f;
                if (cb + 1 > rlo)     p1 = 0.f;
                if (cb     > rlo + 8) p2 = 0.f;
                if (cb + 1 > rlo + 8) p3 = 0.f;
            }
            l_lo += p0 + p1; l_hi += p2 + p3;
        }
    }
    l_lo += __shfl_xor_sync(0xffffffffu, l_lo, 1);
    l_lo += __shfl_xor_sync(0xffffffffu, l_lo, 2);
    l_hi += __shfl_xor_sync(0xffffffffu, l_hi, 1);
    l_hi += __shfl_xor_sync(0xffffffffu, l_hi, 2);
    if (q2 == 0) { atomicAdd(&ls[rlo], l_lo); atomicAdd(&ls[rlo + 8], l_hi); }

    __syncthreads();
    if (tid < 64) lrl[tid] = -__log2f(ls[tid]);
    __syncthreads();
    float la = lrl[rlo], lb = lrl[rlo + 8];

    float cacc[4][4] = {};

    // -------- phase B: normalized w (stcs) + PV --------
    stageKV(0, 0);
    for (int v = 0; v < nv; v++) {
        __syncthreads();
        if (v + 1 < nv) { stageKV(v + 1, (v + 1) & 1); CP_WAIT1; }
        else            { CP_WAIT0; }
        __syncthreads();
        unsigned kbase = sbase + (2048u + (v & 1)*4096u)*4u;
        unsigned vbase = kbase + 8192u;
        int kp0 = (v % nj) * 64, kb2 = v / nj;
        size_t wrow = ((size_t)((bq*NHh + h)*Bb + kb2)) * Ss + s0;

        float sacc[4][4] = {};
        #pragma unroll
        for (int nt = 0; nt < 4; nt++) {
            unsigned nrow = (wc*4 + nt)*8 + k_row;
            #pragma unroll
            for (int kp = 0; kp < 2; kp++) {
                unsigned b0, b1, b2, b3;
                ldsm4(b0, b1, b2, b3,
                      kbase + swz(nrow*128u + (kp*32 + k_cg*8)*2u));
                mma_f16(sacc[nt], qa[2*kp],     b0, b1);
                mma_f16(sacc[nt], qa[2*kp + 1], b2, b3);
            }
        }

        bool diag = (kp0 == s0);
        #pragma unroll
        for (int nt = 0; nt < 4; nt++) {
            int cb = wc*32 + nt*8 + 2*q2;
            float p0 = exp2f(fmaf(sacc[nt][0], ISC2, la));
            float p1 = exp2f(fmaf(sacc[nt][1], ISC2, la));
            float p2 = exp2f(fmaf(sacc[nt][2], ISC2, lb));
            float p3 = exp2f(fmaf(sacc[nt][3], ISC2, lb));
            if (diag) {
                if (cb     > rlo)     p0 = 0.f;
                if (cb + 1 > rlo)     p1 = 0.f;
                if (cb     > rlo + 8) p2 = 0.f;
                if (cb + 1 > rlo + 8) p3 = 0.f;
            }
            // streaming w writes straight from registers
            __stcs((float2*)(w_out + (wrow + rlo)     * Ss + kp0 + cb), make_float2(p0, p1));
            __stcs((float2*)(w_out + (wrow + rlo + 8) * Ss + kp0 + cb), make_float2(p2, p3));
            // fp16 P into Ps (feeds PV via ldmatrix)
            *(unsigned*)((char*)dsm + 40960u + swz(rlo*128u + cb*2u))       = packh2(p0, p1);
            *(unsigned*)((char*)dsm + 40960u + swz((rlo + 8)*128u + cb*2u)) = packh2(p2, p3);
        }
        __syncthreads();

        // P A-frags
        unsigned pa[4][4];
        #pragma unroll
        for (int ks = 0; ks < 4; ks++) {
            unsigned addr = sbase + 40960u + swz((16*wr + (lane & 15))*128u
                                                 + (ks*16 + (lane >> 4)*8)*2u);
            ldsm4(pa[ks][0], pa[ks][1], pa[ks][2], pa[ks][3], addr);
        }
        // ctx += P V   (V: [key][d] k-major -> .trans ldmatrix)
        #pragma unroll
        for (int nt = 0; nt < 4; nt++) {
            unsigned colb = (wc*32 + nt*8)*2u;
            #pragma unroll
            for (int kp = 0; kp < 2; kp++) {
                unsigned v0, v1, v2, v3;
                ldsm4t(v0, v1, v2, v3,
                       vbase + swz((kp*32 + lane)*128u + colb));
                mma_f16(cacc[nt], pa[2*kp],     v0, v1);
                mma_f16(cacc[nt], pa[2*kp + 1], v2, v3);
            }
        }
    }

    // ctx epilogue -> A-frag tf32 layout (already normalized)
    int rblkg = (r0 >> 4) + wr;
    #pragma unroll
    for (int nt = 0; nt < 4; nt++) {
        size_t kkg = (size_t)(h*8 + wc*4 + nt);
        #pragma unroll
        for (int hi = 0; hi < 2; hi++) {
            #pragma unroll
            for (int j = 0; j < 2; j++) {
                int kbit = 2*q2 + j;
                int word = (4*r4 + (kbit & 3))*4 + hi + 2*((kbit >> 2) & 1);
                g_cf[((size_t)rblkg*64 + kkg)*128 + word] = f2tf32(cacc[nt][2*hi + j]);
            }
        }
    }
}

// ============================================================
// Pipelined 64x64x512 tf32 GEMM core (for out_kernel)
// ============================================================
__device__ __forceinline__ void gemm_pipe(
    const unsigned* __restrict__ abase, const unsigned* __restrict__ wbase,
    unsigned* sA, unsigned* sW, float facc[4][4],
    int tid, int lane, int wr, int wc)
{
    auto stage = [&](int c, int buf) {
        #pragma unroll
        for (int rblk = 0; rblk < 4; rblk++) {
            unsigned dst = (unsigned)__cvta_generic_to_shared(sA + buf*4096 + rblk*1024 + tid*4);
            cp16(dst, abase + (size_t)(rblk*64 + c*8)*128 + tid*4);
        }
        #pragma unroll
        for (int s = 0; s < 4; s++) {
            int idx = tid + 256*s;
            int nb = idx >> 7, rem = idx & 127;
            unsigned dst = (unsigned)__cvta_generic_to_shared(sW + buf*4096 + nb*512 + rem*4);
            cp16(dst, wbase + (size_t)(nb*64 + c*8)*64 + rem*4);
        }
        CP_COMMIT;
    };

    stage(0, 0);
    for (int c = 0; c < 8; c++) {
        __syncthreads();
        if (c + 1 < 8) { stage(c + 1, (c + 1) & 1); CP_WAIT1; }
        else           { CP_WAIT0; }
        __syncthreads();
        const unsigned* A = sA + (c & 1) * 4096;
        const unsigned* W = sW + (c & 1) * 4096;
        #pragma unroll
        for (int kk = 0; kk < 8; kk++) {
            uint4 aa = *(const uint4*)(A + wr*1024 + kk*128 + lane*4);
            #pragma unroll
            for (int nt = 0; nt < 4; nt++) {
                uint2 bb = *(const uint2*)(W + (wc*4 + nt)*512 + kk*64 + lane*2);
                mma_tf32(facc[nt], aa, bb);
            }
        }
    }
}

// ============================================================
// Kernel 3: out_pre = ctx @ Wo^T + enc -> g_tmp
// ============================================================
__global__ __launch_bounds__(256) void out_kernel(const float* __restrict__ enc)
{
    extern __shared__ unsigned dsm[];
    unsigned* sA = dsm;
    unsigned* sW = dsm + 8192;

    int n0 = blockIdx.x * 64, m0 = blockIdx.y * 64;
    int tid = threadIdx.x, lane = tid & 31, wid = tid >> 5;
    int wr = wid >> 1, wc = wid & 1;

    float facc[4][4] = {};
    gemm_pipe(g_cf + (size_t)(m0 >> 4)*64*128,
              g_wf + (size_t)(3*64 + (n0 >> 3))*64*64,
              sA, sW, facc, tid, lane, wr, wc);

    int q2 = lane & 3, r4 = lane >> 2;
    #pragma unroll
    for (int nt = 0; nt < 4; nt++) {
        #pragma unroll
        for (int hi = 0; hi < 2; hi++) {
            int row = m0 + 16*wr + r4 + 8*hi;
            int col = n0 + wc*32 + nt*8 + 2*q2;
            float2 e2 = *(const float2*)(enc + (size_t)row * HIDD + col);
            float2 o = make_float2(facc[nt][2*hi] + e2.x, facc[nt][2*hi + 1] + e2.y);
            *(float2*)(g_tmp + (size_t)row * HIDD + col) = o;
        }
    }
}

// ============================================================
// Kernel 4: per-row LayerNorm -> d_out[0 : R*HID]
// ============================================================
__global__ __launch_bounds__(256) void ln_kernel(
    const float* __restrict__ gamma,
    const float* __restrict__ beta,
    float* __restrict__ out)
{
    int r = blockIdx.x;
    int t = threadIdx.x;
    const float* x = g_tmp + (size_t)r * HIDD;
    float v0 = x[t], v1 = x[t + 256];

    __shared__ float red[256];
    red[t] = v0 + v1;
    __syncthreads();
    #pragma unroll
    for (int o = 128; o > 0; o >>= 1) {
        if (t < o) red[t] += red[t + o];
        __syncthreads();
    }
    float mu = red[0] * (1.0f / HIDD);
    __syncthreads();

    float d0 = v0 - mu, d1 = v1 - mu;
    red[t] = d0*d0 + d1*d1;
    __syncthreads();
    #pragma unroll
    for (int o = 128; o > 0; o >>= 1) {
        if (t < o) red[t] += red[t + o];
        __syncthreads();
    }
    float var = red[0] * (1.0f / HIDD);
    float rs = rsqrtf(var + 1e-6f);

    out[(size_t)r * HIDD + t]       = d0 * rs * gamma[t]       + beta[t];
    out[(size_t)r * HIDD + t + 256] = d1 * rs * gamma[t + 256] + beta[t + 256];
}

// ============================================================
// launch
// ============================================================
extern "C" void kernel_launch(void* const* d_in, const int* in_sizes, int n_in,
                              void* d_out, int out_size)
{
    const float* enc   = (const float*)d_in[0];
    // d_in[1] = mask (int32 tril) — reproduced analytically
    const float* Wq    = (const float*)d_in[2];
    const float* Wk    = (const float*)d_in[3];
    const float* Wv    = (const float*)d_in[4];
    const float* Wo    = (const float*)d_in[5];
    const float* gamma = (const float*)d_in[6];
    const float* beta  = (const float*)d_in[7];

    float* out = (float*)d_out;                  // (B,S,HID)
    float* w   = out + (size_t)RR * HIDD;        // (B,NH,B,S,S)

    const int qkv_smem  = 16384 * 4;             // 64 KB
    const int gemm_smem = 16384 * 4;             // 64 KB
    const int attn_smem = 12416 * 4;             // 49664 B -> 3 CTAs/SM
    cudaFuncSetAttribute(qkv_kernel,  cudaFuncAttributeMaxDynamicSharedMemorySize, qkv_smem);
    cudaFuncSetAttribute(out_kernel,  cudaFuncAttributeMaxDynamicSharedMemorySize, gemm_smem);
    cudaFuncSetAttribute(attn_kernel, cudaFuncAttributeMaxDynamicSharedMemorySize, attn_smem);

    prep_kernel<<<640, 256>>>(enc, Wq, Wk, Wv, Wo);
    qkv_kernel<<<dim3(8, 48), 256, qkv_smem>>>();
    attn_kernel<<<384, 256, attn_smem>>>(w);
    out_kernel<<<dim3(8, 48), 256, gemm_smem>>>(enc);
    ln_kernel<<<RR, 256>>>(gamma, beta, out);
}

// round 14
// speedup vs baseline: 1.3605x; 1.1046x over previous
#include <cuda_runtime.h>
#include <cuda_fp16.h>

#define Bb 8
#define Ss 384
#define HIDD 512
#define NHh 8
#define HDd 64
#define RR (Bb*Ss)            // 3072 rows
#define ISC2   0.063763263477419631f       // (1/sqrt(512)) * log2(e)

// ---- scratch (device globals; no allocation allowed) ----
static __device__ __align__(16) unsigned short g_eh[RR*HIDD];     // enc fp16 [row][k]
static __device__ __align__(16) unsigned short g_wh[4*HIDD*HIDD]; // W fp16 [mat][n][k]
static __device__ __align__(16) unsigned short g_qh[NHh*RR*HDd];  // Q fp16 [h][row][d]
static __device__ __align__(16) unsigned short g_kh[NHh*RR*HDd];  // K fp16 [h][key][d]
static __device__ __align__(16) unsigned short g_vh[NHh*RR*HDd];  // V fp16 [h][key][d]
static __device__ __align__(16) unsigned short g_ch[RR*HIDD];     // ctx fp16 [row][col]
static __device__ float g_tmp[RR*HIDD];

__device__ __forceinline__ unsigned packh2(float lo, float hi) {
    unsigned u; asm("cvt.rn.f16x2.f32 %0, %1, %2;" : "=r"(u) : "f"(hi), "f"(lo)); return u;
}
__device__ __forceinline__ void mma_f16(float d[4], const unsigned a[4],
                                        unsigned b0, unsigned b1) {
    asm volatile(
      "mma.sync.aligned.m16n8k16.row.col.f32.f16.f16.f32 "
      "{%0,%1,%2,%3}, {%4,%5,%6,%7}, {%8,%9}, {%0,%1,%2,%3};\n"
      : "+f"(d[0]), "+f"(d[1]), "+f"(d[2]), "+f"(d[3])
      : "r"(a[0]), "r"(a[1]), "r"(a[2]), "r"(a[3]), "r"(b0), "r"(b1));
}
__device__ __forceinline__ void ldsm4(unsigned& r0, unsigned& r1, unsigned& r2,
                                      unsigned& r3, unsigned addr) {
    asm volatile("ldmatrix.sync.aligned.m8n8.x4.shared.b16 {%0,%1,%2,%3}, [%4];"
                 : "=r"(r0), "=r"(r1), "=r"(r2), "=r"(r3) : "r"(addr));
}
__device__ __forceinline__ void ldsm4t(unsigned& r0, unsigned& r1, unsigned& r2,
                                       unsigned& r3, unsigned addr) {
    asm volatile("ldmatrix.sync.aligned.m8n8.x4.trans.shared.b16 {%0,%1,%2,%3}, [%4];"
                 : "=r"(r0), "=r"(r1), "=r"(r2), "=r"(r3) : "r"(addr));
}
__device__ __forceinline__ unsigned swz(unsigned o) { return o ^ ((o >> 3) & 0x70u); }

__device__ __forceinline__ void cp16(unsigned dst_smem, const void* src) {
    asm volatile("cp.async.cg.shared.global [%0], [%1], 16;\n"
                 :: "r"(dst_smem), "l"(src));
}
#define CP_COMMIT asm volatile("cp.async.commit_group;\n" ::: "memory")
#define CP_WAIT1  asm volatile("cp.async.wait_group 1;\n" ::: "memory")
#define CP_WAIT0  asm volatile("cp.async.wait_group 0;\n" ::: "memory")

// ============================================================
// Kernel 0: fp32 -> fp16 convert: enc -> g_eh, W -> g_wh.
// grid 2560 x 256; one float4 per thread.
// ============================================================
__global__ __launch_bounds__(256) void prep_kernel(
    const float* __restrict__ enc, const float* __restrict__ Wq,
    const float* __restrict__ Wk,  const float* __restrict__ Wv,
    const float* __restrict__ Wo)
{
    int g = blockIdx.x * 256 + threadIdx.x;          // float4 index
    if (blockIdx.x < 1536) {
        float4 v = ((const float4*)enc)[g];
        *(uint2*)&g_eh[4*(size_t)g] =
            make_uint2(packh2(v.x, v.y), packh2(v.z, v.w));
    } else {
        int i = g - 1536*256;                        // 0..262143
        int mat = i >> 16;
        int off = i & 65535;
        const float* W = (mat == 0) ? Wq : (mat == 1) ? Wk : (mat == 2) ? Wv : Wo;
        float4 v = ((const float4*)W)[off];
        *(uint2*)&g_wh[((size_t)mat << 18) + 4*(size_t)off] =
            make_uint2(packh2(v.x, v.y), packh2(v.z, v.w));
    }
}

// ============================================================
// Kernel 1: Q/K/V projections, fp16 GEMM (ldmatrix + m16n8k16),
// z-fused: A staged once per chunk, 3 W tiles.
// smem: buf = A 2048w | W0 2048w | W1 2048w | W2 2048w, x2 = 64KB
// grid (8 heads, 48 m-tiles), block 256
// ============================================================
__global__ __launch_bounds__(256) void qkv_kernel()
{
    extern __shared__ unsigned dsm[];
    unsigned sbase = (unsigned)__cvta_generic_to_shared(dsm);

    int h = blockIdx.x, m0 = blockIdx.y * 64;
    int tid = threadIdx.x, lane = tid & 31, wid = tid >> 5;
    int wr = wid >> 1, wc = wid & 1;
    unsigned k_row = lane & 7, k_cg = (lane >> 3) & 3;

    auto stage = [&](int c, int buf) {
        unsigned b = sbase + (unsigned)buf * 8192u * 4u;
        const unsigned short* asrc = g_eh + (size_t)m0*HIDD + c*64;
        #pragma unroll
        for (int s = 0; s < 2; s++) {
            int ch = tid + 256*s;                    // 0..511
            cp16(b + swz(ch*16), asrc + (size_t)(ch >> 3)*HIDD + (ch & 7)*8);
        }
        #pragma unroll
        for (int z = 0; z < 3; z++) {
            const unsigned short* wsrc = g_wh + ((size_t)z*HIDD + h*64)*HIDD + c*64;
            #pragma unroll
            for (int s = 0; s < 2; s++) {
                int ch = tid + 256*s;
                cp16(b + (2048u + z*2048u)*4u + swz(ch*16),
                     wsrc + (size_t)(ch >> 3)*HIDD + (ch & 7)*8);
            }
        }
        CP_COMMIT;
    };

    float facc[3][4][4] = {};

    stage(0, 0);
    for (int c = 0; c < 8; c++) {
        __syncthreads();
        if (c + 1 < 8) { stage(c + 1, (c + 1) & 1); CP_WAIT1; }
        else           { CP_WAIT0; }
        __syncthreads();
        unsigned b = sbase + (unsigned)(c & 1) * 8192u * 4u;

        unsigned qa[4][4];
        #pragma unroll
        for (int ks = 0; ks < 4; ks++)
            ldsm4(qa[ks][0], qa[ks][1], qa[ks][2], qa[ks][3],
                  b + swz((16*wr + (lane & 15))*128u + (ks*16 + (lane >> 4)*8)*2u));

        #pragma unroll
        for (int z = 0; z < 3; z++) {
            unsigned wb = b + (2048u + z*2048u)*4u;
            #pragma unroll
            for (int nt = 0; nt < 4; nt++) {
                unsigned nrow = (wc*4 + nt)*8 + k_row;
                #pragma unroll
                for (int kp = 0; kp < 2; kp++) {
                    unsigned b0, b1, b2, b3;
                    ldsm4(b0, b1, b2, b3,
                          wb + swz(nrow*128u + (kp*32 + k_cg*8)*2u));
                    mma_f16(facc[z][nt], qa[2*kp],     b0, b1);
                    mma_f16(facc[z][nt], qa[2*kp + 1], b2, b3);
                }
            }
        }
    }

    // epilogue: plain fp16 [h][row][d]
    int q2 = lane & 3, r4 = lane >> 2;
    #pragma unroll
    for (int z = 0; z < 3; z++) {
        unsigned short* outp = (z == 0) ? g_qh : ((z == 1) ? g_kh : g_vh);
        #pragma unroll
        for (int nt = 0; nt < 4; nt++) {
            int cb = wc*32 + nt*8 + 2*q2;
            #pragma unroll
            for (int hi = 0; hi < 2; hi++) {
                int gr = m0 + 16*wr + r4 + 8*hi;
                unsigned u = packh2(facc[z][nt][2*hi], facc[z][nt][2*hi + 1]);
                *(unsigned*)&outp[((size_t)h*RR + gr)*HDd + cb] = u;
            }
        }
    }
}

// ============================================================
// Kernel 2: attention fp16 (R13-proven), fused A+B, heavy-first,
// stcs w writes; ctx epilogue -> plain fp16 g_ch.
// ============================================================
__global__ __launch_bounds__(256, 3) void attn_kernel(float* __restrict__ w_out)
{
    extern __shared__ unsigned dsm[];
    unsigned sbase = (unsigned)__cvta_generic_to_shared(dsm);
    float* ls  = (float*)(dsm + 12288);
    float* lrl = (float*)(dsm + 12352);

    int tid = threadIdx.x, lane = tid & 31, wid = tid >> 5;
    int wr = wid >> 1, wc = wid & 1;

    int bid = blockIdx.x;
    int c   = bid >> 6;
    int nj  = 6 - c;
    int e   = bid & 63;
    int h   = e & 7, bq = e >> 3;
    int s0  = (nj - 1) * 64;
    int r0  = bq * Ss + s0;
    int nv  = 8 * nj;

    int q2 = lane & 3, r4 = lane >> 2;
    int rlo = 16*wr + r4;
    int lrr = tid >> 4, lcc = (tid & 15) * 4;

    if (tid < 64) ls[tid] = 0.f;

    // stage Q tile (8KB)
    {
        const unsigned short* src = g_qh + ((size_t)h*RR + r0)*HDd;
        #pragma unroll
        for (int s = 0; s < 2; s++) {
            int ch = tid + 256*s;
            cp16(sbase + swz(ch*16), src + (ch >> 3)*64 + (ch & 7)*8);
        }
        CP_COMMIT;
    }

    // masked tiles: zero w-writes while Q stages
    for (int kb = 0; kb < 8; kb++)
        for (int j = nj; j < 6; j++) {
            size_t wrow = ((size_t)((bq*NHh + h)*Bb + kb)) * Ss;
            float4 z4 = make_float4(0.f, 0.f, 0.f, 0.f);
            #pragma unroll
            for (int i = 0; i < 4; i++)
                __stcs((float4*)(w_out + (wrow + s0 + lrr + 16*i) * Ss + j*64 + lcc), z4);
        }

    CP_WAIT0;
    __syncthreads();

    unsigned qa[4][4];
    #pragma unroll
    for (int ks = 0; ks < 4; ks++) {
        unsigned addr = sbase + swz((16*wr + (lane & 15))*128u
                                    + (ks*16 + (lane >> 4)*8)*2u);
        ldsm4(qa[ks][0], qa[ks][1], qa[ks][2], qa[ks][3], addr);
    }

    auto stageK = [&](int v, int buf) {
        int kt = (v/nj)*6 + (v % nj);
        const unsigned short* src = g_kh + ((size_t)h*RR + kt*64)*HDd;
        unsigned kb = sbase + (2048u + buf*4096u)*4u;
        #pragma unroll
        for (int s = 0; s < 2; s++) {
            int ch = tid + 256*s;
            cp16(kb + swz(ch*16), src + (ch >> 3)*64 + (ch & 7)*8);
        }
        CP_COMMIT;
    };
    auto stageKV = [&](int v, int buf) {
        int kt = (v/nj)*6 + (v % nj);
        const unsigned short* ks = g_kh + ((size_t)h*RR + kt*64)*HDd;
        const unsigned short* vs = g_vh + ((size_t)h*RR + kt*64)*HDd;
        unsigned kb = sbase + (2048u + buf*4096u)*4u;
        unsigned vb = kb + 8192u;
        #pragma unroll
        for (int s = 0; s < 2; s++) {
            int ch = tid + 256*s;
            cp16(kb + swz(ch*16), ks + (ch >> 3)*64 + (ch & 7)*8);
            cp16(vb + swz(ch*16), vs + (ch >> 3)*64 + (ch & 7)*8);
        }
        CP_COMMIT;
    };

    unsigned k_row = (lane & 7);
    unsigned k_cg  = ((lane >> 3) & 3);

    // -------- phase A: row sums in registers --------
    float l_lo = 0.f, l_hi = 0.f;
    stageK(0, 0);
    for (int v = 0; v < nv; v++) {
        __syncthreads();
        if (v + 1 < nv) { stageK(v + 1, (v + 1) & 1); CP_WAIT1; }
        else            { CP_WAIT0; }
        __syncthreads();
        unsigned kbase = sbase + (2048u + (v & 1)*4096u)*4u;
        int kp0 = (v % nj) * 64;

        float sacc[4][4] = {};
        #pragma unroll
        for (int nt = 0; nt < 4; nt++) {
            unsigned nrow = (wc*4 + nt)*8 + k_row;
            #pragma unroll
            for (int kp = 0; kp < 2; kp++) {
                unsigned b0, b1, b2, b3;
                ldsm4(b0, b1, b2, b3,
                      kbase + swz(nrow*128u + (kp*32 + k_cg*8)*2u));
                mma_f16(sacc[nt], qa[2*kp],     b0, b1);
                mma_f16(sacc[nt], qa[2*kp + 1], b2, b3);
            }
        }

        bool diag = (kp0 == s0);
        #pragma unroll
        for (int nt = 0; nt < 4; nt++) {
            int cb = wc*32 + nt*8 + 2*q2;
            float p0 = exp2f(sacc[nt][0] * ISC2);
            float p1 = exp2f(sacc[nt][1] * ISC2);
            float p2 = exp2f(sacc[nt][2] * ISC2);
            float p3 = exp2f(sacc[nt][3] * ISC2);
            if (diag) {
                if (cb     > rlo)     p0 = 0.f;
                if (cb + 1 > rlo)     p1 = 0.f;
                if (cb     > rlo + 8) p2 = 0.f;
                if (cb + 1 > rlo + 8) p3 = 0.f;
            }
            l_lo += p0 + p1; l_hi += p2 + p3;
        }
    }
    l_lo += __shfl_xor_sync(0xffffffffu, l_lo, 1);
    l_lo += __shfl_xor_sync(0xffffffffu, l_lo, 2);
    l_hi += __shfl_xor_sync(0xffffffffu, l_hi, 1);
    l_hi += __shfl_xor_sync(0xffffffffu, l_hi, 2);
    if (q2 == 0) { atomicAdd(&ls[rlo], l_lo); atomicAdd(&ls[rlo + 8], l_hi); }

    __syncthreads();
    if (tid < 64) lrl[tid] = -__log2f(ls[tid]);
    __syncthreads();
    float la = lrl[rlo], lb = lrl[rlo + 8];

    float cacc[4][4] = {};

    // -------- phase B: normalized w (stcs) + PV --------
    stageKV(0, 0);
    for (int v = 0; v < nv; v++) {
        __syncthreads();
        if (v + 1 < nv) { stageKV(v + 1, (v + 1) & 1); CP_WAIT1; }
        else            { CP_WAIT0; }
        __syncthreads();
        unsigned kbase = sbase + (2048u + (v & 1)*4096u)*4u;
        unsigned vbase = kbase + 8192u;
        int kp0 = (v % nj) * 64, kb2 = v / nj;
        size_t wrow = ((size_t)((bq*NHh + h)*Bb + kb2)) * Ss + s0;

        float sacc[4][4] = {};
        #pragma unroll
        for (int nt = 0; nt < 4; nt++) {
            unsigned nrow = (wc*4 + nt)*8 + k_row;
            #pragma unroll
            for (int kp = 0; kp < 2; kp++) {
                unsigned b0, b1, b2, b3;
                ldsm4(b0, b1, b2, b3,
                      kbase + swz(nrow*128u + (kp*32 + k_cg*8)*2u));
                mma_f16(sacc[nt], qa[2*kp],     b0, b1);
                mma_f16(sacc[nt], qa[2*kp + 1], b2, b3);
            }
        }

        bool diag = (kp0 == s0);
        #pragma unroll
        for (int nt = 0; nt < 4; nt++) {
            int cb = wc*32 + nt*8 + 2*q2;
            float p0 = exp2f(fmaf(sacc[nt][0], ISC2, la));
            float p1 = exp2f(fmaf(sacc[nt][1], ISC2, la));
            float p2 = exp2f(fmaf(sacc[nt][2], ISC2, lb));
            float p3 = exp2f(fmaf(sacc[nt][3], ISC2, lb));
            if (diag) {
                if (cb     > rlo)     p0 = 0.f;
                if (cb + 1 > rlo)     p1 = 0.f;
                if (cb     > rlo + 8) p2 = 0.f;
                if (cb + 1 > rlo + 8) p3 = 0.f;
            }
            __stcs((float2*)(w_out + (wrow + rlo)     * Ss + kp0 + cb), make_float2(p0, p1));
            __stcs((float2*)(w_out + (wrow + rlo + 8) * Ss + kp0 + cb), make_float2(p2, p3));
            *(unsigned*)((char*)dsm + 40960u + swz(rlo*128u + cb*2u))       = packh2(p0, p1);
            *(unsigned*)((char*)dsm + 40960u + swz((rlo + 8)*128u + cb*2u)) = packh2(p2, p3);
        }
        __syncthreads();

        unsigned pa[4][4];
        #pragma unroll
        for (int ks = 0; ks < 4; ks++) {
            unsigned addr = sbase + 40960u + swz((16*wr + (lane & 15))*128u
                                                 + (ks*16 + (lane >> 4)*8)*2u);
            ldsm4(pa[ks][0], pa[ks][1], pa[ks][2], pa[ks][3], addr);
        }
        #pragma unroll
        for (int nt = 0; nt < 4; nt++) {
            unsigned colb = (wc*32 + nt*8)*2u;
            #pragma unroll
            for (int kp = 0; kp < 2; kp++) {
                unsigned v0, v1, v2, v3;
                ldsm4t(v0, v1, v2, v3,
                       vbase + swz((kp*32 + lane)*128u + colb));
                mma_f16(cacc[nt], pa[2*kp],     v0, v1);
                mma_f16(cacc[nt], pa[2*kp + 1], v2, v3);
            }
        }
    }

    // ctx epilogue -> plain fp16 [row][col] (already normalized)
    #pragma unroll
    for (int nt = 0; nt < 4; nt++) {
        int cb = wc*32 + nt*8 + 2*q2;
        #pragma unroll
        for (int hi = 0; hi < 2; hi++) {
            int row = r0 + rlo + 8*hi;
            *(unsigned*)&g_ch[(size_t)row*HIDD + h*HDd + cb] =
                packh2(cacc[nt][2*hi], cacc[nt][2*hi + 1]);
        }
    }
}

// ============================================================
// Kernel 3: out_pre = ctx @ Wo^T + enc -> g_tmp (fp16 GEMM)
// smem: buf = A 2048w | W 2048w, x2 = 32KB
// grid (8 n-tiles, 48 m-tiles), block 256
// ============================================================
__global__ __launch_bounds__(256) void out_kernel(const float* __restrict__ enc)
{
    extern __shared__ unsigned dsm[];
    unsigned sbase = (unsigned)__cvta_generic_to_shared(dsm);

    int n0 = blockIdx.x * 64, m0 = blockIdx.y * 64;
    int tid = threadIdx.x, lane = tid & 31, wid = tid >> 5;
    int wr = wid >> 1, wc = wid & 1;
    unsigned k_row = lane & 7, k_cg = (lane >> 3) & 3;

    auto stage = [&](int c, int buf) {
        unsigned b = sbase + (unsigned)buf * 4096u * 4u;
        const unsigned short* asrc = g_ch + (size_t)m0*HIDD + c*64;
        const unsigned short* wsrc = g_wh + ((size_t)3*HIDD + n0)*HIDD + c*64;
        #pragma unroll
        for (int s = 0; s < 2; s++) {
            int ch = tid + 256*s;
            cp16(b + swz(ch*16), asrc + (size_t)(ch >> 3)*HIDD + (ch & 7)*8);
            cp16(b + 8192u + swz(ch*16), wsrc + (size_t)(ch >> 3)*HIDD + (ch & 7)*8);
        }
        CP_COMMIT;
    };

    float facc[4][4] = {};

    stage(0, 0);
    for (int c = 0; c < 8; c++) {
        __syncthreads();
        if (c + 1 < 8) { stage(c + 1, (c + 1) & 1); CP_WAIT1; }
        else           { CP_WAIT0; }
        __syncthreads();
        unsigned b = sbase + (unsigned)(c & 1) * 4096u * 4u;

        unsigned qa[4][4];
        #pragma unroll
        for (int ks = 0; ks < 4; ks++)
            ldsm4(qa[ks][0], qa[ks][1], qa[ks][2], qa[ks][3],
                  b + swz((16*wr + (lane & 15))*128u + (ks*16 + (lane >> 4)*8)*2u));

        #pragma unroll
        for (int nt = 0; nt < 4; nt++) {
            unsigned nrow = (wc*4 + nt)*8 + k_row;
            #pragma unroll
            for (int kp = 0; kp < 2; kp++) {
                unsigned b0, b1, b2, b3;
                ldsm4(b0, b1, b2, b3,
                      b + 8192u + swz(nrow*128u + (kp*32 + k_cg*8)*2u));
                mma_f16(facc[nt], qa[2*kp],     b0, b1);
                mma_f16(facc[nt], qa[2*kp + 1], b2, b3);
            }
        }
    }

    int q2 = lane & 3, r4 = lane >> 2;
    #pragma unroll
    for (int nt = 0; nt < 4; nt++) {
        #pragma unroll
        for (int hi = 0; hi < 2; hi++) {
            int row = m0 + 16*wr + r4 + 8*hi;
            int col = n0 + wc*32 + nt*8 + 2*q2;
            float2 e2 = *(const float2*)(enc + (size_t)row * HIDD + col);
            float2 o = make_float2(facc[nt][2*hi] + e2.x, facc[nt][2*hi + 1] + e2.y);
            *(float2*)(g_tmp + (size_t)row * HIDD + col) = o;
        }
    }
}

// ============================================================
// Kernel 4: per-row LayerNorm -> d_out[0 : R*HID]
// ============================================================
__global__ __launch_bounds__(256) void ln_kernel(
    const float* __restrict__ gamma,
    const float* __restrict__ beta,
    float* __restrict__ out)
{
    int r = blockIdx.x;
    int t = threadIdx.x;
    const float* x = g_tmp + (size_t)r * HIDD;
    float v0 = x[t], v1 = x[t + 256];

    __shared__ float red[256];
    red[t] = v0 + v1;
    __syncthreads();
    #pragma unroll
    for (int o = 128; o > 0; o >>= 1) {
        if (t < o) red[t] += red[t + o];
        __syncthreads();
    }
    float mu = red[0] * (1.0f / HIDD);
    __syncthreads();

    float d0 = v0 - mu, d1 = v1 - mu;
    red[t] = d0*d0 + d1*d1;
    __syncthreads();
    #pragma unroll
    for (int o = 128; o > 0; o >>= 1) {
        if (t < o) red[t] += red[t + o];
        __syncthreads();
    }
    float var = red[0] * (1.0f / HIDD);
    float rs = rsqrtf(var + 1e-6f);

    out[(size_t)r * HIDD + t]       = d0 * rs * gamma[t]       + beta[t];
    out[(size_t)r * HIDD + t + 256] = d1 * rs * gamma[t + 256] + beta[t + 256];
}

// ============================================================
// launch
// ============================================================
extern "C" void kernel_launch(void* const* d_in, const int* in_sizes, int n_in,
                              void* d_out, int out_size)
{
    const float* enc   = (const float*)d_in[0];
    // d_in[1] = mask (int32 tril) — reproduced analytically
    const float* Wq    = (const float*)d_in[2];
    const float* Wk    = (const float*)d_in[3];
    const float* Wv    = (const float*)d_in[4];
    const float* Wo    = (const float*)d_in[5];
    const float* gamma = (const float*)d_in[6];
    const float* beta  = (const float*)d_in[7];

    float* out = (float*)d_out;                  // (B,S,HID)
    float* w   = out + (size_t)RR * HIDD;        // (B,NH,B,S,S)

    const int qkv_smem  = 16384 * 4;             // 64 KB
    const int out_smem  = 8192 * 4;              // 32 KB
    const int attn_smem = 12416 * 4;             // 49664 B -> 3 CTAs/SM
    cudaFuncSetAttribute(qkv_kernel,  cudaFuncAttributeMaxDynamicSharedMemorySize, qkv_smem);
    cudaFuncSetAttribute(out_kernel,  cudaFuncAttributeMaxDynamicSharedMemorySize, out_smem);
    cudaFuncSetAttribute(attn_kernel, cudaFuncAttributeMaxDynamicSharedMemorySize, attn_smem);

    prep_kernel<<<2560, 256>>>(enc, Wq, Wk, Wv, Wo);
    qkv_kernel<<<dim3(8, 48), 256, qkv_smem>>>();
    attn_kernel<<<384, 256, attn_smem>>>(w);
    out_kernel<<<dim3(8, 48), 256, out_smem>>>(enc);
    ln_kernel<<<RR, 256>>>(gamma, beta, out);
}

// round 15
// speedup vs baseline: 1.4588x; 1.0722x over previous
#include <cuda_runtime.h>
#include <cuda_fp16.h>

#define Bb 8
#define Ss 384
#define HIDD 512
#define NHh 8
#define HDd 64
#define RR (Bb*Ss)            // 3072 rows
#define ISC2   0.063763263477419631f       // (1/sqrt(512)) * log2(e)

// ---- scratch (device globals; no allocation allowed) ----
static __device__ __align__(16) unsigned short g_eh[RR*HIDD];     // enc fp16 [row][k]
static __device__ __align__(16) unsigned short g_wh[4*HIDD*HIDD]; // W fp16 [mat][n][k]
static __device__ __align__(16) unsigned short g_qh[NHh*RR*HDd];  // Q fp16 [h][row][d]
static __device__ __align__(16) unsigned short g_kh[NHh*RR*HDd];  // K fp16 [h][key][d]
static __device__ __align__(16) unsigned short g_vh[NHh*RR*HDd];  // V fp16 [h][key][d]
static __device__ __align__(16) float g_ls[NHh*RR];               // row sums (atomic)
static __device__ __align__(16) float g_ctxf[RR*HIDD];            // ctx fp32 (atomic)
static __device__ __align__(16) unsigned short g_ch[RR*HIDD];     // ctx fp16 [row][col]
static __device__ float g_tmp[RR*HIDD];

__device__ __forceinline__ unsigned packh2(float lo, float hi) {
    unsigned u; asm("cvt.rn.f16x2.f32 %0, %1, %2;" : "=r"(u) : "f"(hi), "f"(lo)); return u;
}
__device__ __forceinline__ void mma_f16(float d[4], const unsigned a[4],
                                        unsigned b0, unsigned b1) {
    asm volatile(
      "mma.sync.aligned.m16n8k16.row.col.f32.f16.f16.f32 "
      "{%0,%1,%2,%3}, {%4,%5,%6,%7}, {%8,%9}, {%0,%1,%2,%3};\n"
      : "+f"(d[0]), "+f"(d[1]), "+f"(d[2]), "+f"(d[3])
      : "r"(a[0]), "r"(a[1]), "r"(a[2]), "r"(a[3]), "r"(b0), "r"(b1));
}
__device__ __forceinline__ void ldsm4(unsigned& r0, unsigned& r1, unsigned& r2,
                                      unsigned& r3, unsigned addr) {
    asm volatile("ldmatrix.sync.aligned.m8n8.x4.shared.b16 {%0,%1,%2,%3}, [%4];"
                 : "=r"(r0), "=r"(r1), "=r"(r2), "=r"(r3) : "r"(addr));
}
__device__ __forceinline__ void ldsm4t(unsigned& r0, unsigned& r1, unsigned& r2,
                                       unsigned& r3, unsigned addr) {
    asm volatile("ldmatrix.sync.aligned.m8n8.x4.trans.shared.b16 {%0,%1,%2,%3}, [%4];"
                 : "=r"(r0), "=r"(r1), "=r"(r2), "=r"(r3) : "r"(addr));
}
__device__ __forceinline__ unsigned swz(unsigned o) { return o ^ ((o >> 3) & 0x70u); }

__device__ __forceinline__ void cp16(unsigned dst_smem, const void* src) {
    asm volatile("cp.async.cg.shared.global [%0], [%1], 16;\n"
                 :: "r"(dst_smem), "l"(src));
}
#define CP_COMMIT asm volatile("cp.async.commit_group;\n" ::: "memory")
#define CP_WAIT1  asm volatile("cp.async.wait_group 1;\n" ::: "memory")
#define CP_WAIT0  asm volatile("cp.async.wait_group 0;\n" ::: "memory")

// balanced block map (shared by attn_a / attn_b): 576 blocks, LPT order.
// nj>=4 classes split into kb halves; per-block tiles <= 24 per phase.
__device__ __forceinline__ void block_map(int bid, int& nj, int& kb0, int& nkb, int& e)
{
    if (bid < 128)      { nj = 6; kb0 = (bid >> 6)*4;        nkb = 4; e = bid & 63; }
    else if (bid < 192) { nj = 3; kb0 = 0;                   nkb = 8; e = bid - 128; }
    else if (bid < 320) { nj = 5; kb0 = ((bid-192) >> 6)*4;  nkb = 4; e = (bid-192) & 63; }
    else if (bid < 448) { nj = 4; kb0 = ((bid-320) >> 6)*4;  nkb = 4; e = (bid-320) & 63; }
    else if (bid < 512) { nj = 2; kb0 = 0;                   nkb = 8; e = bid - 448; }
    else                { nj = 1; kb0 = 0;                   nkb = 8; e = bid - 512; }
}

// ============================================================
// Kernel 0: fp32->fp16 convert (enc, W) + zero g_ls, g_ctxf.
// grid 4120 x 256
// ============================================================
__global__ __launch_bounds__(256) void prep_kernel(
    const float* __restrict__ enc, const float* __restrict__ Wq,
    const float* __restrict__ Wk,  const float* __restrict__ Wv,
    const float* __restrict__ Wo)
{
    int bid = blockIdx.x;
    int g = bid * 256 + threadIdx.x;
    if (bid < 1536) {
        float4 v = ((const float4*)enc)[g];
        *(uint2*)&g_eh[4*(size_t)g] =
            make_uint2(packh2(v.x, v.y), packh2(v.z, v.w));
    } else if (bid < 2560) {
        int i = g - 1536*256;
        int mat = i >> 16;
        int off = i & 65535;
        const float* W = (mat == 0) ? Wq : (mat == 1) ? Wk : (mat == 2) ? Wv : Wo;
        float4 v = ((const float4*)W)[off];
        *(uint2*)&g_wh[((size_t)mat << 18) + 4*(size_t)off] =
            make_uint2(packh2(v.x, v.y), packh2(v.z, v.w));
    } else if (bid < 2584) {
        int i = g - 2560*256;      // 0..6143 float4 of g_ls
        ((float4*)g_ls)[i] = make_float4(0.f, 0.f, 0.f, 0.f);
    } else {
        int i = g - 2584*256;      // 0..393215 float4 of g_ctxf
        ((float4*)g_ctxf)[i] = make_float4(0.f, 0.f, 0.f, 0.f);
    }
}

// ============================================================
// Kernel 1: Q/K/V projections, fp16 GEMM, z-fused (R14-proven).
// ============================================================
__global__ __launch_bounds__(256) void qkv_kernel()
{
    extern __shared__ unsigned dsm[];
    unsigned sbase = (unsigned)__cvta_generic_to_shared(dsm);

    int h = blockIdx.x, m0 = blockIdx.y * 64;
    int tid = threadIdx.x, lane = tid & 31, wid = tid >> 5;
    int wr = wid >> 1, wc = wid & 1;
    unsigned k_row = lane & 7, k_cg = (lane >> 3) & 3;

    auto stage = [&](int c, int buf) {
        unsigned b = sbase + (unsigned)buf * 8192u * 4u;
        const unsigned short* asrc = g_eh + (size_t)m0*HIDD + c*64;
        #pragma unroll
        for (int s = 0; s < 2; s++) {
            int ch = tid + 256*s;
            cp16(b + swz(ch*16), asrc + (size_t)(ch >> 3)*HIDD + (ch & 7)*8);
        }
        #pragma unroll
        for (int z = 0; z < 3; z++) {
            const unsigned short* wsrc = g_wh + ((size_t)z*HIDD + h*64)*HIDD + c*64;
            #pragma unroll
            for (int s = 0; s < 2; s++) {
                int ch = tid + 256*s;
                cp16(b + (2048u + z*2048u)*4u + swz(ch*16),
                     wsrc + (size_t)(ch >> 3)*HIDD + (ch & 7)*8);
            }
        }
        CP_COMMIT;
    };

    float facc[3][4][4] = {};

    stage(0, 0);
    for (int c = 0; c < 8; c++) {
        __syncthreads();
        if (c + 1 < 8) { stage(c + 1, (c + 1) & 1); CP_WAIT1; }
        else           { CP_WAIT0; }
        __syncthreads();
        unsigned b = sbase + (unsigned)(c & 1) * 8192u * 4u;

        unsigned qa[4][4];
        #pragma unroll
        for (int ks = 0; ks < 4; ks++)
            ldsm4(qa[ks][0], qa[ks][1], qa[ks][2], qa[ks][3],
                  b + swz((16*wr + (lane & 15))*128u + (ks*16 + (lane >> 4)*8)*2u));

        #pragma unroll
        for (int z = 0; z < 3; z++) {
            unsigned wb = b + (2048u + z*2048u)*4u;
            #pragma unroll
            for (int nt = 0; nt < 4; nt++) {
                unsigned nrow = (wc*4 + nt)*8 + k_row;
                #pragma unroll
                for (int kp = 0; kp < 2; kp++) {
                    unsigned b0, b1, b2, b3;
                    ldsm4(b0, b1, b2, b3,
                          wb + swz(nrow*128u + (kp*32 + k_cg*8)*2u));
                    mma_f16(facc[z][nt], qa[2*kp],     b0, b1);
                    mma_f16(facc[z][nt], qa[2*kp + 1], b2, b3);
                }
            }
        }
    }

    int q2 = lane & 3, r4 = lane >> 2;
    #pragma unroll
    for (int z = 0; z < 3; z++) {
        unsigned short* outp = (z == 0) ? g_qh : ((z == 1) ? g_kh : g_vh);
        #pragma unroll
        for (int nt = 0; nt < 4; nt++) {
            int cb = wc*32 + nt*8 + 2*q2;
            #pragma unroll
            for (int hi = 0; hi < 2; hi++) {
                int gr = m0 + 16*wr + r4 + 8*hi;
                unsigned u = packh2(facc[z][nt][2*hi], facc[z][nt][2*hi + 1]);
                *(unsigned*)&outp[((size_t)h*RR + gr)*HDd + cb] = u;
            }
        }
    }
}

// ============================================================
// Kernel 2a: attention phase A (balanced 576 blocks, 4 CTA/SM):
// QK^T + exp + partial row sums -> atomicAdd g_ls. Zeroes masked w.
// smem: Q 2048w | K bufs 2048w x2 = 24576 B
// ============================================================
__global__ __launch_bounds__(256, 4) void attn_a_kernel(float* __restrict__ w_out)
{
    extern __shared__ unsigned dsm[];
    unsigned sbase = (unsigned)__cvta_generic_to_shared(dsm);

    int tid = threadIdx.x, lane = tid & 31, wid = tid >> 5;
    int wr = wid >> 1, wc = wid & 1;

    int nj, kb0, nkb, e;
    block_map(blockIdx.x, nj, kb0, nkb, e);
    int h = e & 7, bq = e >> 3;
    int s0 = (nj - 1) * 64;
    int r0 = bq * Ss + s0;
    int nv = nkb * nj;

    int q2 = lane & 3, r4 = lane >> 2;
    int rlo = 16*wr + r4;
    int lrr = tid >> 4, lcc = (tid & 15) * 4;

    // stage Q tile
    {
        const unsigned short* src = g_qh + ((size_t)h*RR + r0)*HDd;
        #pragma unroll
        for (int s = 0; s < 2; s++) {
            int ch = tid + 256*s;
            cp16(sbase + swz(ch*16), src + (ch >> 3)*64 + (ch & 7)*8);
        }
        CP_COMMIT;
    }

    // masked tiles for this block's kb range
    for (int kb = kb0; kb < kb0 + nkb; kb++)
        for (int j = nj; j < 6; j++) {
            size_t wrow = ((size_t)((bq*NHh + h)*Bb + kb)) * Ss;
            float4 z4 = make_float4(0.f, 0.f, 0.f, 0.f);
            #pragma unroll
            for (int i = 0; i < 4; i++)
                __stcs((float4*)(w_out + (wrow + s0 + lrr + 16*i) * Ss + j*64 + lcc), z4);
        }

    CP_WAIT0;
    __syncthreads();

    unsigned qa[4][4];
    #pragma unroll
    for (int ks = 0; ks < 4; ks++) {
        unsigned addr = sbase + swz((16*wr + (lane & 15))*128u
                                    + (ks*16 + (lane >> 4)*8)*2u);
        ldsm4(qa[ks][0], qa[ks][1], qa[ks][2], qa[ks][3], addr);
    }

    auto stageK = [&](int v, int buf) {
        int kt = (kb0 + v/nj)*6 + (v % nj);
        const unsigned short* src = g_kh + ((size_t)h*RR + kt*64)*HDd;
        unsigned kb = sbase + (2048u + buf*2048u)*4u;
        #pragma unroll
        for (int s = 0; s < 2; s++) {
            int ch = tid + 256*s;
            cp16(kb + swz(ch*16), src + (ch >> 3)*64 + (ch & 7)*8);
        }
        CP_COMMIT;
    };

    unsigned k_row = (lane & 7), k_cg = ((lane >> 3) & 3);

    float l_lo = 0.f, l_hi = 0.f;
    stageK(0, 0);
    for (int v = 0; v < nv; v++) {
        __syncthreads();
        if (v + 1 < nv) { stageK(v + 1, (v + 1) & 1); CP_WAIT1; }
        else            { CP_WAIT0; }
        __syncthreads();
        unsigned kbase = sbase + (2048u + (v & 1)*2048u)*4u;
        int kp0 = (v % nj) * 64;

        float sacc[4][4] = {};
        #pragma unroll
        for (int nt = 0; nt < 4; nt++) {
            unsigned nrow = (wc*4 + nt)*8 + k_row;
            #pragma unroll
            for (int kp = 0; kp < 2; kp++) {
                unsigned b0, b1, b2, b3;
                ldsm4(b0, b1, b2, b3,
                      kbase + swz(nrow*128u + (kp*32 + k_cg*8)*2u));
                mma_f16(sacc[nt], qa[2*kp],     b0, b1);
                mma_f16(sacc[nt], qa[2*kp + 1], b2, b3);
            }
        }

        bool diag = (kp0 == s0);
        #pragma unroll
        for (int nt = 0; nt < 4; nt++) {
            int cb = wc*32 + nt*8 + 2*q2;
            float p0 = exp2f(sacc[nt][0] * ISC2);
            float p1 = exp2f(sacc[nt][1] * ISC2);
            float p2 = exp2f(sacc[nt][2] * ISC2);
            float p3 = exp2f(sacc[nt][3] * ISC2);
            if (diag) {
                if (cb     > rlo)     p0 = 0.f;
                if (cb + 1 > rlo)     p1 = 0.f;
                if (cb     > rlo + 8) p2 = 0.f;
                if (cb + 1 > rlo + 8) p3 = 0.f;
            }
            l_lo += p0 + p1; l_hi += p2 + p3;
        }
    }
    l_lo += __shfl_xor_sync(0xffffffffu, l_lo, 1);
    l_lo += __shfl_xor_sync(0xffffffffu, l_lo, 2);
    l_hi += __shfl_xor_sync(0xffffffffu, l_hi, 1);
    l_hi += __shfl_xor_sync(0xffffffffu, l_hi, 2);
    if (q2 == 0) {
        atomicAdd(&g_ls[h*RR + r0 + rlo],     l_lo);
        atomicAdd(&g_ls[h*RR + r0 + rlo + 8], l_hi);
    }
}

// ============================================================
// Kernel 2b: attention phase B (balanced 576 blocks, 3 CTA/SM):
// QK^T + normalized w (stcs) + PV; ctx -> atomicAdd g_ctxf.
// smem: Q 2048w | KV bufs 4096w x2 | Ps 2048w = 49152 B
// ============================================================
__global__ __launch_bounds__(256, 3) void attn_b_kernel(float* __restrict__ w_out)
{
    extern __shared__ unsigned dsm[];
    unsigned sbase = (unsigned)__cvta_generic_to_shared(dsm);

    int tid = threadIdx.x, lane = tid & 31, wid = tid >> 5;
    int wr = wid >> 1, wc = wid & 1;

    int nj, kb0, nkb, e;
    block_map(blockIdx.x, nj, kb0, nkb, e);
    int h = e & 7, bq = e >> 3;
    int s0 = (nj - 1) * 64;
    int r0 = bq * Ss + s0;
    int nv = nkb * nj;

    int q2 = lane & 3, r4 = lane >> 2;
    int rlo = 16*wr + r4;

    // stage Q tile
    {
        const unsigned short* src = g_qh + ((size_t)h*RR + r0)*HDd;
        #pragma unroll
        for (int s = 0; s < 2; s++) {
            int ch = tid + 256*s;
            cp16(sbase + swz(ch*16), src + (ch >> 3)*64 + (ch & 7)*8);
        }
        CP_COMMIT;
    }

    float la = -__log2f(g_ls[h*RR + r0 + rlo]);
    float lb = -__log2f(g_ls[h*RR + r0 + rlo + 8]);

    CP_WAIT0;
    __syncthreads();

    unsigned qa[4][4];
    #pragma unroll
    for (int ks = 0; ks < 4; ks++) {
        unsigned addr = sbase + swz((16*wr + (lane & 15))*128u
                                    + (ks*16 + (lane >> 4)*8)*2u);
        ldsm4(qa[ks][0], qa[ks][1], qa[ks][2], qa[ks][3], addr);
    }

    auto stageKV = [&](int v, int buf) {
        int kt = (kb0 + v/nj)*6 + (v % nj);
        const unsigned short* ks = g_kh + ((size_t)h*RR + kt*64)*HDd;
        const unsigned short* vs = g_vh + ((size_t)h*RR + kt*64)*HDd;
        unsigned kb = sbase + (2048u + buf*4096u)*4u;
        unsigned vb = kb + 8192u;
        #pragma unroll
        for (int s = 0; s < 2; s++) {
            int ch = tid + 256*s;
            cp16(kb + swz(ch*16), ks + (ch >> 3)*64 + (ch & 7)*8);
            cp16(vb + swz(ch*16), vs + (ch >> 3)*64 + (ch & 7)*8);
        }
        CP_COMMIT;
    };

    unsigned k_row = (lane & 7), k_cg = ((lane >> 3) & 3);
    float cacc[4][4] = {};

    stageKV(0, 0);
    for (int v = 0; v < nv; v++) {
        __syncthreads();
        if (v + 1 < nv) { stageKV(v + 1, (v + 1) & 1); CP_WAIT1; }
        else            { CP_WAIT0; }
        __syncthreads();
        unsigned kbase = sbase + (2048u + (v & 1)*4096u)*4u;
        unsigned vbase = kbase + 8192u;
        int kp0 = (v % nj) * 64, kb2 = kb0 + v / nj;
        size_t wrow = ((size_t)((bq*NHh + h)*Bb + kb2)) * Ss + s0;

        float sacc[4][4] = {};
        #pragma unroll
        for (int nt = 0; nt < 4; nt++) {
            unsigned nrow = (wc*4 + nt)*8 + k_row;
            #pragma unroll
            for (int kp = 0; kp < 2; kp++) {
                unsigned b0, b1, b2, b3;
                ldsm4(b0, b1, b2, b3,
                      kbase + swz(nrow*128u + (kp*32 + k_cg*8)*2u));
                mma_f16(sacc[nt], qa[2*kp],     b0, b1);
                mma_f16(sacc[nt], qa[2*kp + 1], b2, b3);
            }
        }

        bool diag = (kp0 == s0);
        #pragma unroll
        for (int nt = 0; nt < 4; nt++) {
            int cb = wc*32 + nt*8 + 2*q2;
            float p0 = exp2f(fmaf(sacc[nt][0], ISC2, la));
            float p1 = exp2f(fmaf(sacc[nt][1], ISC2, la));
            float p2 = exp2f(fmaf(sacc[nt][2], ISC2, lb));
            float p3 = exp2f(fmaf(sacc[nt][3], ISC2, lb));
            if (diag) {
                if (cb     > rlo)     p0 = 0.f;
                if (cb + 1 > rlo)     p1 = 0.f;
                if (cb     > rlo + 8) p2 = 0.f;
                if (cb + 1 > rlo + 8) p3 = 0.f;
            }
            __stcs((float2*)(w_out + (wrow + rlo)     * Ss + kp0 + cb), make_float2(p0, p1));
            __stcs((float2*)(w_out + (wrow + rlo + 8) * Ss + kp0 + cb), make_float2(p2, p3));
            *(unsigned*)((char*)dsm + 40960u + swz(rlo*128u + cb*2u))       = packh2(p0, p1);
            *(unsigned*)((char*)dsm + 40960u + swz((rlo + 8)*128u + cb*2u)) = packh2(p2, p3);
        }
        __syncthreads();

        unsigned pa[4][4];
        #pragma unroll
        for (int ks = 0; ks < 4; ks++) {
            unsigned addr = sbase + 40960u + swz((16*wr + (lane & 15))*128u
                                                 + (ks*16 + (lane >> 4)*8)*2u);
            ldsm4(pa[ks][0], pa[ks][1], pa[ks][2], pa[ks][3], addr);
        }
        #pragma unroll
        for (int nt = 0; nt < 4; nt++) {
            unsigned colb = (wc*32 + nt*8)*2u;
            #pragma unroll
            for (int kp = 0; kp < 2; kp++) {
                unsigned v0, v1, v2, v3;
                ldsm4t(v0, v1, v2, v3,
                       vbase + swz((kp*32 + lane)*128u + colb));
                mma_f16(cacc[nt], pa[2*kp],     v0, v1);
                mma_f16(cacc[nt], pa[2*kp + 1], v2, v3);
            }
        }
    }

    // ctx partial -> fp32 atomic accumulation (<=2 contributors: deterministic)
    #pragma unroll
    for (int nt = 0; nt < 4; nt++) {
        int cb = wc*32 + nt*8 + 2*q2;
        #pragma unroll
        for (int hi = 0; hi < 2; hi++) {
            int row = r0 + rlo + 8*hi;
            float* dst = &g_ctxf[(size_t)row*HIDD + h*HDd + cb];
            atomicAdd(dst,     cacc[nt][2*hi]);
            atomicAdd(dst + 1, cacc[nt][2*hi + 1]);
        }
    }
}

// ============================================================
// Kernel 2c: ctx fp32 -> fp16 convert. grid 1536 x 256.
// ============================================================
__global__ __launch_bounds__(256) void cvt_kernel()
{
    int g = blockIdx.x * 256 + threadIdx.x;
    float4 v = ((const float4*)g_ctxf)[g];
    *(uint2*)&g_ch[4*(size_t)g] = make_uint2(packh2(v.x, v.y), packh2(v.z, v.w));
}

// ============================================================
// Kernel 3: out_pre = ctx @ Wo^T + enc -> g_tmp (fp16 GEMM)
// ============================================================
__global__ __launch_bounds__(256) void out_kernel(const float* __restrict__ enc)
{
    extern __shared__ unsigned dsm[];
    unsigned sbase = (unsigned)__cvta_generic_to_shared(dsm);

    int n0 = blockIdx.x * 64, m0 = blockIdx.y * 64;
    int tid = threadIdx.x, lane = tid & 31, wid = tid >> 5;
    int wr = wid >> 1, wc = wid & 1;
    unsigned k_row = lane & 7, k_cg = (lane >> 3) & 3;

    auto stage = [&](int c, int buf) {
        unsigned b = sbase + (unsigned)buf * 4096u * 4u;
        const unsigned short* asrc = g_ch + (size_t)m0*HIDD + c*64;
        const unsigned short* wsrc = g_wh + ((size_t)3*HIDD + n0)*HIDD + c*64;
        #pragma unroll
        for (int s = 0; s < 2; s++) {
            int ch = tid + 256*s;
            cp16(b + swz(ch*16), asrc + (size_t)(ch >> 3)*HIDD + (ch & 7)*8);
            cp16(b + 8192u + swz(ch*16), wsrc + (size_t)(ch >> 3)*HIDD + (ch & 7)*8);
        }
        CP_COMMIT;
    };

    float facc[4][4] = {};

    stage(0, 0);
    for (int c = 0; c < 8; c++) {
        __syncthreads();
        if (c + 1 < 8) { stage(c + 1, (c + 1) & 1); CP_WAIT1; }
        else           { CP_WAIT0; }
        __syncthreads();
        unsigned b = sbase + (unsigned)(c & 1) * 4096u * 4u;

        unsigned qa[4][4];
        #pragma unroll
        for (int ks = 0; ks < 4; ks++)
            ldsm4(qa[ks][0], qa[ks][1], qa[ks][2], qa[ks][3],
                  b + swz((16*wr + (lane & 15))*128u + (ks*16 + (lane >> 4)*8)*2u));

        #pragma unroll
        for (int nt = 0; nt < 4; nt++) {
            unsigned nrow = (wc*4 + nt)*8 + k_row;
            #pragma unroll
            for (int kp = 0; kp < 2; kp++) {
                unsigned b0, b1, b2, b3;
                ldsm4(b0, b1, b2, b3,
                      b + 8192u + swz(nrow*128u + (kp*32 + k_cg*8)*2u));
                mma_f16(facc[nt], qa[2*kp],     b0, b1);
                mma_f16(facc[nt], qa[2*kp + 1], b2, b3);
            }
        }
    }

    int q2 = lane & 3, r4 = lane >> 2;
    #pragma unroll
    for (int nt = 0; nt < 4; nt++) {
        #pragma unroll
        for (int hi = 0; hi < 2; hi++) {
            int row = m0 + 16*wr + r4 + 8*hi;
            int col = n0 + wc*32 + nt*8 + 2*q2;
            float2 e2 = *(const float2*)(enc + (size_t)row * HIDD + col);
            float2 o = make_float2(facc[nt][2*hi] + e2.x, facc[nt][2*hi + 1] + e2.y);
            *(float2*)(g_tmp + (size_t)row * HIDD + col) = o;
        }
    }
}

// ============================================================
// Kernel 4: per-row LayerNorm -> d_out[0 : R*HID]
// ============================================================
__global__ __launch_bounds__(256) void ln_kernel(
    const float* __restrict__ gamma,
    const float* __restrict__ beta,
    float* __restrict__ out)
{
    int r = blockIdx.x;
    int t = threadIdx.x;
    const float* x = g_tmp + (size_t)r * HIDD;
    float v0 = x[t], v1 = x[t + 256];

    __shared__ float red[256];
    red[t] = v0 + v1;
    __syncthreads();
    #pragma unroll
    for (int o = 128; o > 0; o >>= 1) {
        if (t < o) red[t] += red[t + o];
        __syncthreads();
    }
    float mu = red[0] * (1.0f / HIDD);
    __syncthreads();

    float d0 = v0 - mu, d1 = v1 - mu;
    red[t] = d0*d0 + d1*d1;
    __syncthreads();
    #pragma unroll
    for (int o = 128; o > 0; o >>= 1) {
        if (t < o) red[t] += red[t + o];
        __syncthreads();
    }
    float var = red[0] * (1.0f / HIDD);
    float rs = rsqrtf(var + 1e-6f);

    out[(size_t)r * HIDD + t]       = d0 * rs * gamma[t]       + beta[t];
    out[(size_t)r * HIDD + t + 256] = d1 * rs * gamma[t + 256] + beta[t + 256];
}

// ============================================================
// launch
// ============================================================
extern "C" void kernel_launch(void* const* d_in, const int* in_sizes, int n_in,
                              void* d_out, int out_size)
{
    const float* enc   = (const float*)d_in[0];
    // d_in[1] = mask (int32 tril) — reproduced analytically
    const float* Wq    = (const float*)d_in[2];
    const float* Wk    = (const float*)d_in[3];
    const float* Wv    = (const float*)d_in[4];
    const float* Wo    = (const float*)d_in[5];
    const float* gamma = (const float*)d_in[6];
    const float* beta  = (const float*)d_in[7];

    float* out = (float*)d_out;                  // (B,S,HID)
    float* w   = out + (size_t)RR * HIDD;        // (B,NH,B,S,S)

    const int qkv_smem  = 16384 * 4;             // 64 KB
    const int out_smem  = 8192 * 4;              // 32 KB
    const int atta_smem = 6144 * 4;              // 24576 B -> 4 CTAs/SM
    const int attb_smem = 12288 * 4;             // 49152 B -> 3 CTAs/SM
    cudaFuncSetAttribute(qkv_kernel,    cudaFuncAttributeMaxDynamicSharedMemorySize, qkv_smem);
    cudaFuncSetAttribute(out_kernel,    cudaFuncAttributeMaxDynamicSharedMemorySize, out_smem);
    cudaFuncSetAttribute(attn_a_kernel, cudaFuncAttributeMaxDynamicSharedMemorySize, atta_smem);
    cudaFuncSetAttribute(attn_b_kernel, cudaFuncAttributeMaxDynamicSharedMemorySize, attb_smem);

    prep_kernel<<<4120, 256>>>(enc, Wq, Wk, Wv, Wo);
    qkv_kernel<<<dim3(8, 48), 256, qkv_smem>>>();
    attn_a_kernel<<<576, 256, atta_smem>>>(w);
    attn_b_kernel<<<576, 256, attb_smem>>>(w);
    cvt_kernel<<<1536, 256>>>();
    out_kernel<<<dim3(8, 48), 256, out_smem>>>(enc);
    ln_kernel<<<RR, 256>>>(gamma, beta, out);
}